// round 3
// baseline (speedup 1.0000x reference)
#include <cuda_runtime.h>

// ---------------- problem constants ----------------
#define B_SZ   16384
#define NFEAT  32
#define DDIM   64
#define KIN    2048     // NFEAT*DDIM
#define H1     1024
#define H2N    512
#define HOFD   64
#define NPAIRS 496
#define BN_EPS 1e-5f

// ---------------- scratch (device globals; no runtime alloc allowed) -------
__device__ float g_a1[(size_t)B_SZ * H1];   // relu(flat@W1+b1), pre-BN
__device__ float g_h2[(size_t)B_SZ * H2N];  // relu(h1n@W2+b2), pre-BN
__device__ float g_pd[B_SZ];                // pairs . Wc_pairs per batch row
__device__ float g_sum1[H1], g_sq1[H1], g_scale1[H1], g_bias1[H1];
__device__ float g_sum2[H2N], g_sq2[H2N], g_scale2[H2N], g_bias2[H2N];
__device__ float g_w3c[H2N + 1];            // W3@Wc folded, last slot = b3@Wc + bc

// ---------------- zero the stat accumulators (graph replays!) --------------
__global__ void zero_stats() {
    int i = blockIdx.x * blockDim.x + threadIdx.x;
    if (i < H1)  { g_sum1[i] = 0.f; g_sq1[i] = 0.f; }
    if (i < H2N) { g_sum2[i] = 0.f; g_sq2[i] = 0.f; }
}

// ---------------- pair term: pd[b] = sum_{i<j} (x_i . x_j) * Wc[64+p] ------
__global__ __launch_bounds__(256) void pairdot_kernel(
    const float* __restrict__ x, const float* __restrict__ Wc,
    float* __restrict__ pd)
{
    __shared__ float xs[KIN];
    __shared__ float wsum[8];
    const int b = blockIdx.x;
    const float4* xb = (const float4*)(x + (size_t)b * KIN);
    float4* xs4 = (float4*)xs;
    for (int i = threadIdx.x; i < KIN / 4; i += 256) xs4[i] = xb[i];
    __syncthreads();

    const int lane = threadIdx.x & 31, warp = threadIdx.x >> 5;
    float acc = 0.f;
    // one warp per pair; lanes split the 64-dim dot (conflict-free LDS)
    for (int p = warp; p < NPAIRS; p += 8) {
        int i = 0, rem = p;
        while (rem >= 31 - i) { rem -= 31 - i; i++; }
        int j = i + 1 + rem;
        const float* xi = &xs[i * DDIM];
        const float* xj = &xs[j * DDIM];
        float partial = xi[lane] * xj[lane] + xi[lane + 32] * xj[lane + 32];
        #pragma unroll
        for (int o = 16; o > 0; o >>= 1)
            partial += __shfl_down_sync(0xffffffffu, partial, o);
        if (lane == 0) acc += partial * Wc[HOFD + p];
    }
    if (lane == 0) wsum[warp] = acc;
    __syncthreads();
    if (threadIdx.x == 0) {
        float t = 0.f;
        #pragma unroll
        for (int w = 0; w < 8; w++) t += wsum[w];
        pd[b] = t;
    }
}

// ---------------- fold W3/Wc: w3c[k] = sum_j W3[k,j]*Wc[j]; [512]=b3@Wc+bc --
__global__ void w3c_kernel(const float* __restrict__ W3,
                           const float* __restrict__ b3,
                           const float* __restrict__ Wc,
                           const float* __restrict__ bc)
{
    int k = blockIdx.x * blockDim.x + threadIdx.x;
    if (k < H2N) {
        float s = 0.f;
        #pragma unroll
        for (int j = 0; j < HOFD; j++) s += W3[k * HOFD + j] * Wc[j];
        g_w3c[k] = s;
    } else if (k == H2N) {
        float s = 0.f;
        #pragma unroll
        for (int j = 0; j < HOFD; j++) s += b3[j] * Wc[j];
        g_w3c[H2N] = s + bc[0];
    }
}

// ---------------- 128x128x8 register-blocked SGEMM, bias + relu ------------
// C[M,N] = relu( A'[M,K] @ Bw[K,N] + bias[N] ),  A' = A*aSc[k]+aBi[k] if AFFINE
template <bool AFFINE>
__global__ __launch_bounds__(256, 2) void sgemm_relu(
    const float* __restrict__ A, const float* __restrict__ Bw,
    const float* __restrict__ bias, float* __restrict__ C,
    int M, int N, int K,
    const float* __restrict__ aSc, const float* __restrict__ aBi)
{
    const int BM = 128, BN = 128, BK = 8;
    __shared__ float As[BK][BM];
    __shared__ float Bs[BK][BN];
    const int tid = threadIdx.x;
    const int tx = tid & 15, ty = tid >> 4;          // 16x16 thread grid, 8x8 tiles
    const int aRow = tid >> 1, aCol = (tid & 1) * 4; // A tile 128x8
    const int bRow = tid >> 5, bCol = (tid & 31) * 4;// B tile 8x128

    const float* Ap = A + (size_t)(blockIdx.y * BM + aRow) * K + aCol;
    const float* Bp = Bw + (size_t)bRow * N + blockIdx.x * BN + bCol;

    float acc[8][8];
    #pragma unroll
    for (int i = 0; i < 8; i++)
        #pragma unroll
        for (int j = 0; j < 8; j++) acc[i][j] = 0.f;

    for (int k0 = 0; k0 < K; k0 += BK) {
        float4 av = *(const float4*)(Ap + k0);
        if (AFFINE) {
            const int kk = k0 + aCol;
            av.x = fmaf(av.x, aSc[kk + 0], aBi[kk + 0]);
            av.y = fmaf(av.y, aSc[kk + 1], aBi[kk + 1]);
            av.z = fmaf(av.z, aSc[kk + 2], aBi[kk + 2]);
            av.w = fmaf(av.w, aSc[kk + 3], aBi[kk + 3]);
        }
        As[aCol + 0][aRow] = av.x;
        As[aCol + 1][aRow] = av.y;
        As[aCol + 2][aRow] = av.z;
        As[aCol + 3][aRow] = av.w;
        *(float4*)&Bs[bRow][bCol] = *(const float4*)(Bp + (size_t)k0 * N);
        __syncthreads();
        #pragma unroll
        for (int kk = 0; kk < BK; kk++) {
            float ar[8], br[8];
            #pragma unroll
            for (int i = 0; i < 8; i++) ar[i] = As[kk][ty * 8 + i];
            #pragma unroll
            for (int j = 0; j < 8; j++) br[j] = Bs[kk][tx * 8 + j];
            #pragma unroll
            for (int i = 0; i < 8; i++)
                #pragma unroll
                for (int j = 0; j < 8; j++)
                    acc[i][j] = fmaf(ar[i], br[j], acc[i][j]);
        }
        __syncthreads();
    }

    const int colBase = blockIdx.x * BN + tx * 8;
    #pragma unroll
    for (int i = 0; i < 8; i++) {
        const int row = blockIdx.y * BM + ty * 8 + i;
        float* Cp = C + (size_t)row * N + colBase;
        #pragma unroll
        for (int j = 0; j < 8; j += 4) {
            float4 v;
            v.x = fmaxf(acc[i][j + 0] + bias[colBase + j + 0], 0.f);
            v.y = fmaxf(acc[i][j + 1] + bias[colBase + j + 1], 0.f);
            v.z = fmaxf(acc[i][j + 2] + bias[colBase + j + 2], 0.f);
            v.w = fmaxf(acc[i][j + 3] + bias[colBase + j + 3], 0.f);
            *(float4*)(Cp + j) = v;
        }
    }
}

// ---------------- per-column sum / sumsq over rows (coalesced tiles) -------
__global__ void colreduce(const float* __restrict__ X, int M, int N,
                          float* __restrict__ sum, float* __restrict__ sq)
{
    const int lane = threadIdx.x & 31;
    const int ty = threadIdx.x >> 5; // 0..7
    const int col = blockIdx.x * 32 + lane;
    const int rowsPer = M / gridDim.y;
    const int r0 = blockIdx.y * rowsPer;
    float s = 0.f, q = 0.f;
    for (int r = r0 + ty; r < r0 + rowsPer; r += 8) {
        float v = X[(size_t)r * N + col];
        s += v;
        q += v * v;
    }
    __shared__ float ss[8][33], qs[8][33];
    ss[ty][lane] = s; qs[ty][lane] = q;
    __syncthreads();
    if (ty == 0) {
        #pragma unroll
        for (int t = 1; t < 8; t++) { s += ss[t][lane]; q += qs[t][lane]; }
        atomicAdd(&sum[col], s);
        atomicAdd(&sq[col], q);
    }
}

// ---------------- stats -> per-column affine: scale = g*rsqrt(var+eps) -----
__global__ void stats_kernel(const float* __restrict__ sum,
                             const float* __restrict__ sq,
                             const float* __restrict__ g,
                             const float* __restrict__ beta,
                             int N, float* __restrict__ scale,
                             float* __restrict__ bOut)
{
    int j = blockIdx.x * blockDim.x + threadIdx.x;
    if (j >= N) return;
    const float invM = 1.f / (float)B_SZ;
    float m = sum[j] * invM;
    float v = sq[j] * invM - m * m;
    float sc = g[j] * rsqrtf(v + BN_EPS);
    scale[j] = sc;
    bOut[j] = beta[j] - m * sc;
}

// ---------------- final: out[b] = (h2n . w3c) + c0 + pd[b] -----------------
__global__ void final_kernel(const float* __restrict__ h2, float* __restrict__ out)
{
    const int gw = (blockIdx.x * blockDim.x + threadIdx.x) >> 5; // warp per row
    const int lane = threadIdx.x & 31;
    if (gw >= B_SZ) return;
    const float* h = h2 + (size_t)gw * H2N;
    float acc = 0.f;
    #pragma unroll 4
    for (int k = lane; k < H2N; k += 32)
        acc += fmaf(h[k], g_scale2[k], g_bias2[k]) * g_w3c[k];
    #pragma unroll
    for (int o = 16; o > 0; o >>= 1)
        acc += __shfl_down_sync(0xffffffffu, acc, o);
    if (lane == 0) out[gw] = acc + g_w3c[H2N] + g_pd[gw];
}

// ---------------- launch ---------------------------------------------------
extern "C" void kernel_launch(void* const* d_in, const int* in_sizes, int n_in,
                              void* d_out, int out_size)
{
    const float* x     = (const float*)d_in[0];
    const float* W1    = (const float*)d_in[1];
    const float* b1    = (const float*)d_in[2];
    const float* g1    = (const float*)d_in[3];
    const float* beta1 = (const float*)d_in[4];
    const float* W2    = (const float*)d_in[5];
    const float* b2    = (const float*)d_in[6];
    const float* g2    = (const float*)d_in[7];
    const float* beta2 = (const float*)d_in[8];
    const float* W3    = (const float*)d_in[9];
    const float* b3    = (const float*)d_in[10];
    const float* Wc    = (const float*)d_in[11];
    const float* bc    = (const float*)d_in[12];
    float* out = (float*)d_out;

    float *p_a1, *p_h2, *p_pd;
    float *p_sum1, *p_sq1, *p_scale1, *p_bias1;
    float *p_sum2, *p_sq2, *p_scale2, *p_bias2;
    cudaGetSymbolAddress((void**)&p_a1, g_a1);
    cudaGetSymbolAddress((void**)&p_h2, g_h2);
    cudaGetSymbolAddress((void**)&p_pd, g_pd);
    cudaGetSymbolAddress((void**)&p_sum1, g_sum1);
    cudaGetSymbolAddress((void**)&p_sq1, g_sq1);
    cudaGetSymbolAddress((void**)&p_scale1, g_scale1);
    cudaGetSymbolAddress((void**)&p_bias1, g_bias1);
    cudaGetSymbolAddress((void**)&p_sum2, g_sum2);
    cudaGetSymbolAddress((void**)&p_sq2, g_sq2);
    cudaGetSymbolAddress((void**)&p_scale2, g_scale2);
    cudaGetSymbolAddress((void**)&p_bias2, g_bias2);

    // independent prep
    zero_stats<<<4, 256>>>();
    pairdot_kernel<<<B_SZ, 256>>>(x, Wc, p_pd);
    w3c_kernel<<<3, 256>>>(W3, b3, Wc, bc);

    // layer 1: a1 = relu(flat @ W1 + b1)
    sgemm_relu<false><<<dim3(H1 / 128, B_SZ / 128), 256>>>(
        x, W1, b1, p_a1, B_SZ, H1, KIN, nullptr, nullptr);
    colreduce<<<dim3(H1 / 32, 64), 256>>>(p_a1, B_SZ, H1, p_sum1, p_sq1);
    stats_kernel<<<4, 256>>>(p_sum1, p_sq1, g1, beta1, H1, p_scale1, p_bias1);

    // layer 2: h2 = relu( BN1(a1) @ W2 + b2 ), BN folded into A-load
    sgemm_relu<true><<<dim3(H2N / 128, B_SZ / 128), 256>>>(
        p_a1, W2, b2, p_h2, B_SZ, H2N, H1, p_scale1, p_bias1);
    colreduce<<<dim3(H2N / 32, 64), 256>>>(p_h2, B_SZ, H2N, p_sum2, p_sq2);
    stats_kernel<<<2, 256>>>(p_sum2, p_sq2, g2, beta2, H2N, p_scale2, p_bias2);

    // final: out = BN2(h2) @ (W3@Wc) + (b3@Wc + bc) + pairs@Wc_pairs
    final_kernel<<<(B_SZ * 32) / 256, 256>>>(p_h2, out);
}

// round 7
// speedup vs baseline: 1.8588x; 1.8588x over previous
#include <cuda_runtime.h>
#include <cuda_bf16.h>
#include <cstdint>

// ---------------- problem constants ----------------
#define B_SZ   16384
#define NFEAT  32
#define DDIM   64
#define KIN    2048     // NFEAT*DDIM
#define H1     1024
#define H2N    512
#define HOFD   64
#define NPAIRS 496
#define BN_EPS 1e-5f

// ---------------- scratch (device globals; no runtime alloc) ----------------
__device__ __nv_bfloat16 g_xh[(size_t)B_SZ * KIN];
__device__ __nv_bfloat16 g_xl[(size_t)B_SZ * KIN];
__device__ __nv_bfloat16 g_w1h[(size_t)H1 * KIN];   // [N=H1][K=KIN] transposed
__device__ __nv_bfloat16 g_w1l[(size_t)H1 * KIN];
__device__ __nv_bfloat16 g_a1h[(size_t)B_SZ * H1];  // relu(x@W1+b1) split, pre-BN
__device__ __nv_bfloat16 g_a1l[(size_t)B_SZ * H1];
__device__ __nv_bfloat16 g_w2h[(size_t)H2N * H1];   // [N=H2N][K=H1], scale1 folded
__device__ __nv_bfloat16 g_w2l[(size_t)H2N * H1];
__device__ float g_h2[(size_t)B_SZ * H2N];          // relu(.@W2'+b2eff), pre-BN2
__device__ float g_pd[B_SZ];
__device__ float g_sum1[H1], g_sq1[H1], g_scale1[H1], g_bias1v[H1];
__device__ float g_sum2[H2N], g_sq2[H2N], g_scale2[H2N], g_bias2v[H2N];
__device__ float g_b2eff[H2N];
__device__ float g_w3c[H2N + 1];

// ================= PTX helpers (baseline sm_90-/sm_80-era ISA only) ========
__device__ __forceinline__ uint32_t smem_u32(const void* p) {
    uint32_t a;
    asm("{ .reg .u64 t; cvta.to.shared.u64 t, %1; cvt.u32.u64 %0, t; }"
        : "=r"(a) : "l"(p));
    return a;
}
__device__ __forceinline__ void cpa16(uint32_t s, const void* g) {
    asm volatile("cp.async.cg.shared.global [%0], [%1], 16;" :: "r"(s), "l"(g));
}
#define CP_COMMIT() asm volatile("cp.async.commit_group;" ::: "memory")
#define CP_WAIT2()  asm volatile("cp.async.wait_group 2;" ::: "memory")
#define SWZ(o)      ((o) ^ (((o) >> 3) & 0x70))

__device__ __forceinline__ void ldsm4(uint32_t& r0, uint32_t& r1,
                                      uint32_t& r2, uint32_t& r3, uint32_t a) {
    asm volatile("ldmatrix.sync.aligned.m8n8.x4.shared.b16 {%0,%1,%2,%3}, [%4];"
                 : "=r"(r0), "=r"(r1), "=r"(r2), "=r"(r3) : "r"(a));
}
__device__ __forceinline__ void mma16816(float* c,
                                         uint32_t a0, uint32_t a1, uint32_t a2, uint32_t a3,
                                         uint32_t b0, uint32_t b1) {
    asm volatile("mma.sync.aligned.m16n8k16.row.col.f32.bf16.bf16.f32 "
                 "{%0,%1,%2,%3}, {%4,%5,%6,%7}, {%8,%9}, {%0,%1,%2,%3};"
                 : "+f"(c[0]), "+f"(c[1]), "+f"(c[2]), "+f"(c[3])
                 : "r"(a0), "r"(a1), "r"(a2), "r"(a3), "r"(b0), "r"(b1));
}

// ================= split-bf16 HMMA GEMM =================
// C[M, NTOT] = epi( A @ B^T + bias ), A = Ahi+Alo [M,KDIM], B = Bhi+Blo [NTOT,KDIM]
// 3-term split: Ahi*Bhi + Ahi*Blo + Alo*Bhi (lo*lo dropped, ~2^-16 rel).
// EPI 0: write bf16 hi/lo pair of relu(.)   EPI 1: write fp32 relu(.)
template<int KDIM, int NTOT, int EPI>
__global__ __launch_bounds__(512, 1) void gemm_mma(
    const __nv_bfloat16* __restrict__ Ahi, const __nv_bfloat16* __restrict__ Alo,
    const __nv_bfloat16* __restrict__ Bhi, const __nv_bfloat16* __restrict__ Blo,
    const float* __restrict__ bias,
    __nv_bfloat16* __restrict__ outH, __nv_bfloat16* __restrict__ outL,
    float* __restrict__ outF)
{
    constexpr int S = 4, BK = 64, BN = 256, BM = 128;
    constexpr int T = 3 * KDIM / BK;
    constexpr int STAGE_BYTES = (BM + BN) * 128;  // 48KB: A 16K + B 32K (128B rows)

    extern __shared__ char smraw[];
    const uint32_t sb = (smem_u32(smraw) + 1023) & ~1023u;
    const int tid = threadIdx.x;
    const int wid = tid >> 5, lane = tid & 31;
    const int wm0 = (wid >> 3) * 64;        // 2 warp rows  (m: 0 / 64)
    const int wn0 = (wid & 7) * 32;         // 8 warp cols  (n: 0..224)
    const int m0 = blockIdx.y * BM, n0 = blockIdx.x * BN;

    auto load_stage = [&](int gs) {
        const int b = gs & (S - 1);
        const uint32_t sA = sb + b * STAGE_BYTES;
        const uint32_t sB = sA + BM * 128;
        const int g = gs * BK;
        const int seg = g / KDIM;
        const int kk = g - seg * KDIM;
        const __nv_bfloat16* Ap = (seg == 2) ? Alo : Ahi;
        const __nv_bfloat16* Bp = (seg == 1) ? Blo : Bhi;
        const __nv_bfloat16* Ab = Ap + (size_t)m0 * KDIM + kk;
        const __nv_bfloat16* Bb = Bp + (size_t)n0 * KDIM + kk;
        #pragma unroll
        for (int t = 0; t < BM * 8 / 512; t++) {          // 2 iters
            int c = tid + t * 512;
            int r = c >> 3, ch = c & 7;
            cpa16(sA + SWZ(r * 128 + ch * 16), Ab + (size_t)r * KDIM + ch * 8);
        }
        #pragma unroll
        for (int t = 0; t < BN * 8 / 512; t++) {          // 4 iters
            int c = tid + t * 512;
            int r = c >> 3, ch = c & 7;
            cpa16(sB + SWZ(r * 128 + ch * 16), Bb + (size_t)r * KDIM + ch * 8);
        }
    };

    // prologue: stages 0..2 in flight
    load_stage(0); CP_COMMIT();
    load_stage(1); CP_COMMIT();
    load_stage(2); CP_COMMIT();

    float acc[4][4][4];
    #pragma unroll
    for (int i = 0; i < 4; i++)
        #pragma unroll
        for (int j = 0; j < 4; j++)
            #pragma unroll
            for (int r = 0; r < 4; r++) acc[i][j][r] = 0.f;

    // per-lane ldmatrix row components (byte offsets within tile, pre-swizzle)
    const int aRowOff = (wm0 + (lane & 15)) * 128 + (lane >> 4) * 16;
    const int bRowBase = (wn0 + (lane & 7) + ((lane >> 4) << 3)) * 128 +
                         (((lane >> 3) & 1) << 4);

    for (int i = 0; i < T; ++i) {
        const int b = i & (S - 1);
        CP_WAIT2();
        __syncthreads();
        const uint32_t sA = sb + b * STAGE_BYTES;
        const uint32_t sB = sA + BM * 128;
        #pragma unroll
        for (int ks = 0; ks < 4; ks++) {
            const int kb = ks * 32;   // 16 elems * 2B per k-step
            uint32_t a[4][4];
            #pragma unroll
            for (int mi = 0; mi < 4; mi++)
                ldsm4(a[mi][0], a[mi][1], a[mi][2], a[mi][3],
                      sA + SWZ(aRowOff + mi * 16 * 128 + kb));
            uint32_t bf[2][4];
            #pragma unroll
            for (int gg = 0; gg < 2; gg++)
                ldsm4(bf[gg][0], bf[gg][1], bf[gg][2], bf[gg][3],
                      sB + SWZ(bRowBase + gg * 16 * 128 + kb));
            #pragma unroll
            for (int mi = 0; mi < 4; mi++)
                #pragma unroll
                for (int j = 0; j < 4; j++)
                    mma16816(acc[mi][j], a[mi][0], a[mi][1], a[mi][2], a[mi][3],
                             bf[j >> 1][(j & 1) * 2], bf[j >> 1][(j & 1) * 2 + 1]);
        }
        __syncthreads();
        const int ns = i + 3;
        if (ns < T) load_stage(ns);
        CP_COMMIT();
    }

    // ---------------- epilogue: registers -> gmem ----------------
    #pragma unroll
    for (int j = 0; j < 4; j++) {
        const int col = n0 + wn0 + j * 8 + (lane & 3) * 2;
        const float bi0 = bias[col], bi1 = bias[col + 1];
        #pragma unroll
        for (int mi = 0; mi < 4; mi++) {
            const int row = m0 + wm0 + mi * 16 + (lane >> 2);
            #pragma unroll
            for (int h = 0; h < 2; h++) {   // h=0: row, h=1: row+8
                const int rr = row + h * 8;
                const float v0 = fmaxf(acc[mi][j][2 * h + 0] + bi0, 0.f);
                const float v1 = fmaxf(acc[mi][j][2 * h + 1] + bi1, 0.f);
                if (EPI == 0) {
                    __nv_bfloat16 h0 = __float2bfloat16(v0);
                    __nv_bfloat16 h1 = __float2bfloat16(v1);
                    __nv_bfloat162 ph; ph.x = h0; ph.y = h1;
                    __nv_bfloat162 pl;
                    pl.x = __float2bfloat16(v0 - __bfloat162float(h0));
                    pl.y = __float2bfloat16(v1 - __bfloat162float(h1));
                    *(__nv_bfloat162*)(outH + (size_t)rr * NTOT + col) = ph;
                    *(__nv_bfloat162*)(outL + (size_t)rr * NTOT + col) = pl;
                } else {
                    float2 v; v.x = v0; v.y = v1;
                    *(float2*)(outF + (size_t)rr * NTOT + col) = v;
                }
            }
        }
    }
}

// ================= small kernels =================
__global__ void zero_init(const float* __restrict__ b2) {
    int i = blockIdx.x * blockDim.x + threadIdx.x;
    if (i < H1)  { g_sum1[i] = 0.f; g_sq1[i] = 0.f; }
    if (i < H2N) { g_sum2[i] = 0.f; g_sq2[i] = 0.f; g_b2eff[i] = b2[i]; }
}

// x fp32 -> hi/lo bf16 (row-major [B, KIN])
__global__ __launch_bounds__(256) void conv_x_kernel(const float* __restrict__ x) {
    size_t i = ((size_t)blockIdx.x * 256 + threadIdx.x) * 4;
    float4 v = *(const float4*)(x + i);
    __nv_bfloat16 h0 = __float2bfloat16(v.x), h1 = __float2bfloat16(v.y);
    __nv_bfloat16 h2 = __float2bfloat16(v.z), h3 = __float2bfloat16(v.w);
    __nv_bfloat16 l0 = __float2bfloat16(v.x - __bfloat162float(h0));
    __nv_bfloat16 l1 = __float2bfloat16(v.y - __bfloat162float(h1));
    __nv_bfloat16 l2 = __float2bfloat16(v.z - __bfloat162float(h2));
    __nv_bfloat16 l3 = __float2bfloat16(v.w - __bfloat162float(h3));
    __nv_bfloat162 a, b;
    a.x = h0; a.y = h1; b.x = h2; b.y = h3;
    ((__nv_bfloat162*)(g_xh + i))[0] = a; ((__nv_bfloat162*)(g_xh + i))[1] = b;
    a.x = l0; a.y = l1; b.x = l2; b.y = l3;
    ((__nv_bfloat162*)(g_xl + i))[0] = a; ((__nv_bfloat162*)(g_xl + i))[1] = b;
}

// transpose+split W [K][N] -> oh/ol [N][K]; optional scale1[k] fold
template<int K, int N, bool SCALED>
__global__ __launch_bounds__(256) void conv_w(const float* __restrict__ W,
                                              __nv_bfloat16* __restrict__ oh,
                                              __nv_bfloat16* __restrict__ ol) {
    __shared__ float t[32][33];
    const int lx = threadIdx.x & 31, ly = threadIdx.x >> 5;
    const int k0 = blockIdx.y * 32, n0 = blockIdx.x * 32;
    #pragma unroll
    for (int r = 0; r < 4; r++) {
        int k = k0 + ly + r * 8;
        float v = W[(size_t)k * N + n0 + lx];
        if (SCALED) v *= g_scale1[k];
        t[ly + r * 8][lx] = v;
    }
    __syncthreads();
    #pragma unroll
    for (int r = 0; r < 4; r++) {
        int n = n0 + ly + r * 8;
        float v = t[lx][ly + r * 8];
        __nv_bfloat16 h = __float2bfloat16(v);
        oh[(size_t)n * K + k0 + lx] = h;
        ol[(size_t)n * K + k0 + lx] = __float2bfloat16(v - __bfloat162float(h));
    }
}

// bias2eff[n] += sum_k bias1v[k] * W2[k][n]
__global__ __launch_bounds__(512) void b2eff_acc(const float* __restrict__ W2) {
    const int n = threadIdx.x;
    const int k0 = blockIdx.x * 16;
    float a = 0.f;
    #pragma unroll
    for (int r = 0; r < 16; r++)
        a += g_bias1v[k0 + r] * W2[(size_t)(k0 + r) * H2N + n];
    atomicAdd(&g_b2eff[n], a);
}

// pair term: pd[b] = sum_{i<j} (x_i . x_j) * Wc[64+p]
__global__ __launch_bounds__(256) void pairdot_kernel(
    const float* __restrict__ x, const float* __restrict__ Wc,
    float* __restrict__ pd)
{
    __shared__ float xs[KIN];
    __shared__ float wsum[8];
    const int b = blockIdx.x;
    const float4* xb = (const float4*)(x + (size_t)b * KIN);
    float4* xs4 = (float4*)xs;
    for (int i = threadIdx.x; i < KIN / 4; i += 256) xs4[i] = xb[i];
    __syncthreads();
    const int lane = threadIdx.x & 31, warp = threadIdx.x >> 5;
    float acc = 0.f;
    for (int p = warp; p < NPAIRS; p += 8) {
        int i = 0, rem = p;
        while (rem >= 31 - i) { rem -= 31 - i; i++; }
        int j = i + 1 + rem;
        const float* xi = &xs[i * DDIM];
        const float* xj = &xs[j * DDIM];
        float partial = xi[lane] * xj[lane] + xi[lane + 32] * xj[lane + 32];
        #pragma unroll
        for (int o = 16; o > 0; o >>= 1)
            partial += __shfl_down_sync(0xffffffffu, partial, o);
        if (lane == 0) acc += partial * Wc[HOFD + p];
    }
    if (lane == 0) wsum[warp] = acc;
    __syncthreads();
    if (threadIdx.x == 0) {
        float t = 0.f;
        #pragma unroll
        for (int w = 0; w < 8; w++) t += wsum[w];
        pd[b] = t;
    }
}

__global__ void w3c_kernel(const float* __restrict__ W3,
                           const float* __restrict__ b3,
                           const float* __restrict__ Wc,
                           const float* __restrict__ bc) {
    int k = blockIdx.x * blockDim.x + threadIdx.x;
    if (k < H2N) {
        float s = 0.f;
        #pragma unroll
        for (int j = 0; j < HOFD; j++) s += W3[k * HOFD + j] * Wc[j];
        g_w3c[k] = s;
    } else if (k == H2N) {
        float s = 0.f;
        #pragma unroll
        for (int j = 0; j < HOFD; j++) s += b3[j] * Wc[j];
        g_w3c[H2N] = s + bc[0];
    }
}

// per-column sum/sumsq over bf16 hi/lo pair
__global__ void colreduce_pair(const __nv_bfloat16* __restrict__ Xh,
                               const __nv_bfloat16* __restrict__ Xl,
                               int M, int N,
                               float* __restrict__ sum, float* __restrict__ sq) {
    const int lane = threadIdx.x & 31, ty = threadIdx.x >> 5;
    const int col = blockIdx.x * 32 + lane;
    const int rowsPer = M / gridDim.y;
    const int r0 = blockIdx.y * rowsPer;
    float s = 0.f, q = 0.f;
    for (int r = r0 + ty; r < r0 + rowsPer; r += 8) {
        size_t o = (size_t)r * N + col;
        float v = __bfloat162float(Xh[o]) + __bfloat162float(Xl[o]);
        s += v; q += v * v;
    }
    __shared__ float ss[8][33], qs[8][33];
    ss[ty][lane] = s; qs[ty][lane] = q;
    __syncthreads();
    if (ty == 0) {
        #pragma unroll
        for (int t = 1; t < 8; t++) { s += ss[t][lane]; q += qs[t][lane]; }
        atomicAdd(&sum[col], s);
        atomicAdd(&sq[col], q);
    }
}

__global__ void colreduce(const float* __restrict__ X, int M, int N,
                          float* __restrict__ sum, float* __restrict__ sq) {
    const int lane = threadIdx.x & 31, ty = threadIdx.x >> 5;
    const int col = blockIdx.x * 32 + lane;
    const int rowsPer = M / gridDim.y;
    const int r0 = blockIdx.y * rowsPer;
    float s = 0.f, q = 0.f;
    for (int r = r0 + ty; r < r0 + rowsPer; r += 8) {
        float v = X[(size_t)r * N + col];
        s += v; q += v * v;
    }
    __shared__ float ss[8][33], qs[8][33];
    ss[ty][lane] = s; qs[ty][lane] = q;
    __syncthreads();
    if (ty == 0) {
        #pragma unroll
        for (int t = 1; t < 8; t++) { s += ss[t][lane]; q += qs[t][lane]; }
        atomicAdd(&sum[col], s);
        atomicAdd(&sq[col], q);
    }
}

__global__ void stats_kernel(const float* __restrict__ sum,
                             const float* __restrict__ sq,
                             const float* __restrict__ g,
                             const float* __restrict__ beta,
                             int N, float* __restrict__ scale,
                             float* __restrict__ bOut) {
    int j = blockIdx.x * blockDim.x + threadIdx.x;
    if (j >= N) return;
    const float invM = 1.f / (float)B_SZ;
    float m = sum[j] * invM;
    float v = sq[j] * invM - m * m;
    float sc = g[j] * rsqrtf(v + BN_EPS);
    scale[j] = sc;
    bOut[j] = beta[j] - m * sc;
}

// out[b] = (BN2(h2) . w3c) + c0 + pd[b]
__global__ void final_kernel(const float* __restrict__ h2, float* __restrict__ out) {
    const int gw = (blockIdx.x * blockDim.x + threadIdx.x) >> 5;
    const int lane = threadIdx.x & 31;
    if (gw >= B_SZ) return;
    const float* h = h2 + (size_t)gw * H2N;
    float acc = 0.f;
    #pragma unroll 4
    for (int k = lane; k < H2N; k += 32)
        acc += fmaf(h[k], g_scale2[k], g_bias2v[k]) * g_w3c[k];
    #pragma unroll
    for (int o = 16; o > 0; o >>= 1)
        acc += __shfl_down_sync(0xffffffffu, acc, o);
    if (lane == 0) out[gw] = acc + g_w3c[H2N] + g_pd[gw];
}

// ================= launch =================
extern "C" void kernel_launch(void* const* d_in, const int* in_sizes, int n_in,
                              void* d_out, int out_size) {
    const float* x     = (const float*)d_in[0];
    const float* W1    = (const float*)d_in[1];
    const float* b1    = (const float*)d_in[2];
    const float* g1    = (const float*)d_in[3];
    const float* beta1 = (const float*)d_in[4];
    const float* W2    = (const float*)d_in[5];
    const float* b2    = (const float*)d_in[6];
    const float* g2    = (const float*)d_in[7];
    const float* beta2 = (const float*)d_in[8];
    const float* W3    = (const float*)d_in[9];
    const float* b3    = (const float*)d_in[10];
    const float* Wc    = (const float*)d_in[11];
    const float* bc    = (const float*)d_in[12];
    float* out = (float*)d_out;

    __nv_bfloat16 *p_xh, *p_xl, *p_w1h, *p_w1l, *p_a1h, *p_a1l, *p_w2h, *p_w2l;
    float *p_h2, *p_pd, *p_sum1, *p_sq1, *p_scale1, *p_bias1v;
    float *p_sum2, *p_sq2, *p_scale2, *p_bias2v, *p_b2eff;
    cudaGetSymbolAddress((void**)&p_xh, g_xh);
    cudaGetSymbolAddress((void**)&p_xl, g_xl);
    cudaGetSymbolAddress((void**)&p_w1h, g_w1h);
    cudaGetSymbolAddress((void**)&p_w1l, g_w1l);
    cudaGetSymbolAddress((void**)&p_a1h, g_a1h);
    cudaGetSymbolAddress((void**)&p_a1l, g_a1l);
    cudaGetSymbolAddress((void**)&p_w2h, g_w2h);
    cudaGetSymbolAddress((void**)&p_w2l, g_w2l);
    cudaGetSymbolAddress((void**)&p_h2, g_h2);
    cudaGetSymbolAddress((void**)&p_pd, g_pd);
    cudaGetSymbolAddress((void**)&p_sum1, g_sum1);
    cudaGetSymbolAddress((void**)&p_sq1, g_sq1);
    cudaGetSymbolAddress((void**)&p_scale1, g_scale1);
    cudaGetSymbolAddress((void**)&p_bias1v, g_bias1v);
    cudaGetSymbolAddress((void**)&p_sum2, g_sum2);
    cudaGetSymbolAddress((void**)&p_sq2, g_sq2);
    cudaGetSymbolAddress((void**)&p_scale2, g_scale2);
    cudaGetSymbolAddress((void**)&p_bias2v, g_bias2v);
    cudaGetSymbolAddress((void**)&p_b2eff, g_b2eff);

    const int GSM = 4 * 49152 + 1024;  // 4 stages + alignment slack
    cudaFuncSetAttribute(gemm_mma<KIN, H1, 0>,
                         cudaFuncAttributeMaxDynamicSharedMemorySize, GSM);
    cudaFuncSetAttribute(gemm_mma<H1, H2N, 1>,
                         cudaFuncAttributeMaxDynamicSharedMemorySize, GSM);

    // prep (independent)
    zero_init<<<4, 256>>>(b2);
    conv_x_kernel<<<(B_SZ * KIN / 4) / 256, 256>>>(x);
    conv_w<KIN, H1, false><<<dim3(H1 / 32, KIN / 32), 256>>>(W1, p_w1h, p_w1l);
    pairdot_kernel<<<B_SZ, 256>>>(x, Wc, p_pd);
    w3c_kernel<<<3, 256>>>(W3, b3, Wc, bc);

    // layer 1: a1 = relu(x @ W1 + b1), written as bf16 hi/lo split (pre-BN)
    gemm_mma<KIN, H1, 0><<<dim3(H1 / 256, B_SZ / 128), 512, GSM>>>(
        p_xh, p_xl, p_w1h, p_w1l, b1, p_a1h, p_a1l, nullptr);
    colreduce_pair<<<dim3(H1 / 32, 64), 256>>>(p_a1h, p_a1l, B_SZ, H1, p_sum1, p_sq1);
    stats_kernel<<<4, 256>>>(p_sum1, p_sq1, g1, beta1, H1, p_scale1, p_bias1v);

    // fold BN1 into W2 (scale) and bias2eff (rank-1 bias term)
    conv_w<H1, H2N, true><<<dim3(H2N / 32, H1 / 32), 256>>>(W2, p_w2h, p_w2l);
    b2eff_acc<<<H1 / 16, 512>>>(W2);

    // layer 2: h2 = relu( a1 @ (scale1*W2) + b2eff ), fp32 out (pre-BN2)
    gemm_mma<H1, H2N, 1><<<dim3(H2N / 256, B_SZ / 128), 512, GSM>>>(
        p_a1h, p_a1l, p_w2h, p_w2l, p_b2eff, nullptr, nullptr, p_h2);
    colreduce<<<dim3(H2N / 32, 64), 256>>>(p_h2, B_SZ, H2N, p_sum2, p_sq2);
    stats_kernel<<<2, 256>>>(p_sum2, p_sq2, g2, beta2, H2N, p_scale2, p_bias2v);

    // final: out = BN2(h2) @ (W3@Wc) + (b3@Wc + bc) + pairs@Wc_pairs
    final_kernel<<<(B_SZ * 32) / 256, 256>>>(p_h2, out);
}

// round 8
// speedup vs baseline: 3.2305x; 1.7379x over previous
#include <cuda_runtime.h>
#include <cuda_bf16.h>
#include <cstdint>

// ---------------- problem constants ----------------
#define B_SZ   16384
#define NFEAT  32
#define DDIM   64
#define KIN    2048     // NFEAT*DDIM
#define H1     1024
#define H2N    512
#define HOFD   64
#define NPAIRS 496
#define BN_EPS 1e-5f

// ---------------- scratch (device globals; no runtime alloc) ----------------
__device__ __nv_bfloat16 g_xh[(size_t)B_SZ * KIN];
__device__ __nv_bfloat16 g_xl[(size_t)B_SZ * KIN];
__device__ __nv_bfloat16 g_w1h[(size_t)H1 * KIN];   // [N=H1][K=KIN] transposed
__device__ __nv_bfloat16 g_w1l[(size_t)H1 * KIN];
__device__ __nv_bfloat16 g_a1h[(size_t)B_SZ * H1];  // relu(x@W1+b1) split, pre-BN
__device__ __nv_bfloat16 g_a1l[(size_t)B_SZ * H1];
__device__ __nv_bfloat16 g_w2h[(size_t)H2N * H1];   // [N=H2N][K=H1], scale1 folded
__device__ __nv_bfloat16 g_w2l[(size_t)H2N * H1];
__device__ float g_h2[(size_t)B_SZ * H2N];          // relu(.@W2'+b2eff), pre-BN2
__device__ float g_pd[B_SZ];
__device__ float g_wsym[NFEAT * NFEAT];             // symmetric half-weight matrix
__device__ float g_sum1[H1], g_sq1[H1], g_scale1[H1], g_bias1v[H1];
__device__ float g_sum2[H2N], g_sq2[H2N], g_scale2[H2N], g_bias2v[H2N];
__device__ float g_b2eff[H2N];
__device__ float g_w3c[H2N + 1];

// ================= PTX helpers (baseline sm_90-/sm_80-era ISA only) ========
__device__ __forceinline__ uint32_t smem_u32(const void* p) {
    uint32_t a;
    asm("{ .reg .u64 t; cvta.to.shared.u64 t, %1; cvt.u32.u64 %0, t; }"
        : "=r"(a) : "l"(p));
    return a;
}
__device__ __forceinline__ void cpa16(uint32_t s, const void* g) {
    asm volatile("cp.async.cg.shared.global [%0], [%1], 16;" :: "r"(s), "l"(g));
}
#define CP_COMMIT() asm volatile("cp.async.commit_group;" ::: "memory")
#define CP_WAIT2()  asm volatile("cp.async.wait_group 2;" ::: "memory")
#define SWZ(o)      ((o) ^ (((o) >> 3) & 0x70))

__device__ __forceinline__ void ldsm4(uint32_t& r0, uint32_t& r1,
                                      uint32_t& r2, uint32_t& r3, uint32_t a) {
    asm volatile("ldmatrix.sync.aligned.m8n8.x4.shared.b16 {%0,%1,%2,%3}, [%4];"
                 : "=r"(r0), "=r"(r1), "=r"(r2), "=r"(r3) : "r"(a));
}
__device__ __forceinline__ void mma16816(float* c,
                                         uint32_t a0, uint32_t a1, uint32_t a2, uint32_t a3,
                                         uint32_t b0, uint32_t b1) {
    asm volatile("mma.sync.aligned.m16n8k16.row.col.f32.bf16.bf16.f32 "
                 "{%0,%1,%2,%3}, {%4,%5,%6,%7}, {%8,%9}, {%0,%1,%2,%3};"
                 : "+f"(c[0]), "+f"(c[1]), "+f"(c[2]), "+f"(c[3])
                 : "r"(a0), "r"(a1), "r"(a2), "r"(a3), "r"(b0), "r"(b1));
}

// ================= split-bf16 HMMA GEMM =================
// C[M, NTOT] = epi( A @ B^T + bias ), A = Ahi+Alo [M,KDIM], B = Bhi+Blo [NTOT,KDIM]
// 3-term split: Ahi*Bhi + Ahi*Blo + Alo*Bhi (lo*lo dropped, ~2^-16 rel).
// EPI 0: write bf16 hi/lo pair of relu(.)   EPI 1: write fp32 relu(.)
template<int KDIM, int NTOT, int EPI>
__global__ __launch_bounds__(512, 1) void gemm_mma(
    const __nv_bfloat16* __restrict__ Ahi, const __nv_bfloat16* __restrict__ Alo,
    const __nv_bfloat16* __restrict__ Bhi, const __nv_bfloat16* __restrict__ Blo,
    const float* __restrict__ bias,
    __nv_bfloat16* __restrict__ outH, __nv_bfloat16* __restrict__ outL,
    float* __restrict__ outF)
{
    constexpr int S = 4, BK = 64, BN = 256, BM = 128;
    constexpr int T = 3 * KDIM / BK;
    constexpr int STAGE_BYTES = (BM + BN) * 128;  // 48KB: A 16K + B 32K (128B rows)

    extern __shared__ char smraw[];
    const uint32_t sb = (smem_u32(smraw) + 1023) & ~1023u;
    const int tid = threadIdx.x;
    const int wid = tid >> 5, lane = tid & 31;
    const int wm0 = (wid >> 3) * 64;        // 2 warp rows  (m: 0 / 64)
    const int wn0 = (wid & 7) * 32;         // 8 warp cols  (n: 0..224)
    const int m0 = blockIdx.y * BM, n0 = blockIdx.x * BN;

    auto load_stage = [&](int gs) {
        const int b = gs & (S - 1);
        const uint32_t sA = sb + b * STAGE_BYTES;
        const uint32_t sB = sA + BM * 128;
        const int g = gs * BK;
        const int seg = g / KDIM;
        const int kk = g - seg * KDIM;
        const __nv_bfloat16* Ap = (seg == 2) ? Alo : Ahi;
        const __nv_bfloat16* Bp = (seg == 1) ? Blo : Bhi;
        const __nv_bfloat16* Ab = Ap + (size_t)m0 * KDIM + kk;
        const __nv_bfloat16* Bb = Bp + (size_t)n0 * KDIM + kk;
        #pragma unroll
        for (int t = 0; t < BM * 8 / 512; t++) {          // 2 iters
            int c = tid + t * 512;
            int r = c >> 3, ch = c & 7;
            cpa16(sA + SWZ(r * 128 + ch * 16), Ab + (size_t)r * KDIM + ch * 8);
        }
        #pragma unroll
        for (int t = 0; t < BN * 8 / 512; t++) {          // 4 iters
            int c = tid + t * 512;
            int r = c >> 3, ch = c & 7;
            cpa16(sB + SWZ(r * 128 + ch * 16), Bb + (size_t)r * KDIM + ch * 8);
        }
    };

    // prologue: stages 0..2 in flight
    load_stage(0); CP_COMMIT();
    load_stage(1); CP_COMMIT();
    load_stage(2); CP_COMMIT();

    float acc[4][4][4];
    #pragma unroll
    for (int i = 0; i < 4; i++)
        #pragma unroll
        for (int j = 0; j < 4; j++)
            #pragma unroll
            for (int r = 0; r < 4; r++) acc[i][j][r] = 0.f;

    // per-lane ldmatrix row components (byte offsets within tile, pre-swizzle)
    const int aRowOff = (wm0 + (lane & 15)) * 128 + (lane >> 4) * 16;
    const int bRowBase = (wn0 + (lane & 7) + ((lane >> 4) << 3)) * 128 +
                         (((lane >> 3) & 1) << 4);

    for (int i = 0; i < T; ++i) {
        const int b = i & (S - 1);
        CP_WAIT2();
        __syncthreads();
        const uint32_t sA = sb + b * STAGE_BYTES;
        const uint32_t sB = sA + BM * 128;
        #pragma unroll
        for (int ks = 0; ks < 4; ks++) {
            const int kb = ks * 32;   // 16 elems * 2B per k-step
            uint32_t a[4][4];
            #pragma unroll
            for (int mi = 0; mi < 4; mi++)
                ldsm4(a[mi][0], a[mi][1], a[mi][2], a[mi][3],
                      sA + SWZ(aRowOff + mi * 16 * 128 + kb));
            uint32_t bf[2][4];
            #pragma unroll
            for (int gg = 0; gg < 2; gg++)
                ldsm4(bf[gg][0], bf[gg][1], bf[gg][2], bf[gg][3],
                      sB + SWZ(bRowBase + gg * 16 * 128 + kb));
            #pragma unroll
            for (int mi = 0; mi < 4; mi++)
                #pragma unroll
                for (int j = 0; j < 4; j++)
                    mma16816(acc[mi][j], a[mi][0], a[mi][1], a[mi][2], a[mi][3],
                             bf[j >> 1][(j & 1) * 2], bf[j >> 1][(j & 1) * 2 + 1]);
        }
        __syncthreads();
        const int ns = i + 3;
        if (ns < T) load_stage(ns);
        CP_COMMIT();
    }

    // ---------------- epilogue: registers -> gmem ----------------
    #pragma unroll
    for (int j = 0; j < 4; j++) {
        const int col = n0 + wn0 + j * 8 + (lane & 3) * 2;
        const float bi0 = bias[col], bi1 = bias[col + 1];
        #pragma unroll
        for (int mi = 0; mi < 4; mi++) {
            const int row = m0 + wm0 + mi * 16 + (lane >> 2);
            #pragma unroll
            for (int h = 0; h < 2; h++) {   // h=0: row, h=1: row+8
                const int rr = row + h * 8;
                const float v0 = fmaxf(acc[mi][j][2 * h + 0] + bi0, 0.f);
                const float v1 = fmaxf(acc[mi][j][2 * h + 1] + bi1, 0.f);
                if (EPI == 0) {
                    __nv_bfloat16 h0 = __float2bfloat16(v0);
                    __nv_bfloat16 h1 = __float2bfloat16(v1);
                    __nv_bfloat162 ph; ph.x = h0; ph.y = h1;
                    __nv_bfloat162 pl;
                    pl.x = __float2bfloat16(v0 - __bfloat162float(h0));
                    pl.y = __float2bfloat16(v1 - __bfloat162float(h1));
                    *(__nv_bfloat162*)(outH + (size_t)rr * NTOT + col) = ph;
                    *(__nv_bfloat162*)(outL + (size_t)rr * NTOT + col) = pl;
                } else {
                    float2 v; v.x = v0; v.y = v1;
                    *(float2*)(outF + (size_t)rr * NTOT + col) = v;
                }
            }
        }
    }
}

// ================= small kernels =================
__global__ void zero_init(const float* __restrict__ b2) {
    int i = blockIdx.x * blockDim.x + threadIdx.x;
    if (i < H1)  { g_sum1[i] = 0.f; g_sq1[i] = 0.f; }
    if (i < H2N) { g_sum2[i] = 0.f; g_sq2[i] = 0.f; g_b2eff[i] = b2[i]; }
}

// build symmetric half-weight matrix from Wc pair weights
__global__ void wsym_kernel(const float* __restrict__ Wc) {
    int p = blockIdx.x * blockDim.x + threadIdx.x;
    if (p < NFEAT * NFEAT && (p / NFEAT) == (p % NFEAT)) g_wsym[p] = 0.f;
    if (p >= NPAIRS) return;
    int i = 0, rem = p;
    while (rem >= NFEAT - 1 - i) { rem -= NFEAT - 1 - i; i++; }
    int j = i + 1 + rem;
    float hw = 0.5f * Wc[HOFD + p];
    g_wsym[i * NFEAT + j] = hw;
    g_wsym[j * NFEAT + i] = hw;
}

// x fp32 -> hi/lo bf16 (row-major [B, KIN])
__global__ __launch_bounds__(256) void conv_x_kernel(const float* __restrict__ x) {
    size_t i = ((size_t)blockIdx.x * 256 + threadIdx.x) * 4;
    float4 v = *(const float4*)(x + i);
    __nv_bfloat16 h0 = __float2bfloat16(v.x), h1 = __float2bfloat16(v.y);
    __nv_bfloat16 h2 = __float2bfloat16(v.z), h3 = __float2bfloat16(v.w);
    __nv_bfloat16 l0 = __float2bfloat16(v.x - __bfloat162float(h0));
    __nv_bfloat16 l1 = __float2bfloat16(v.y - __bfloat162float(h1));
    __nv_bfloat16 l2 = __float2bfloat16(v.z - __bfloat162float(h2));
    __nv_bfloat16 l3 = __float2bfloat16(v.w - __bfloat162float(h3));
    __nv_bfloat162 a, b;
    a.x = h0; a.y = h1; b.x = h2; b.y = h3;
    ((__nv_bfloat162*)(g_xh + i))[0] = a; ((__nv_bfloat162*)(g_xh + i))[1] = b;
    a.x = l0; a.y = l1; b.x = l2; b.y = l3;
    ((__nv_bfloat162*)(g_xl + i))[0] = a; ((__nv_bfloat162*)(g_xl + i))[1] = b;
}

// transpose+split W [K][N] -> oh/ol [N][K]; optional scale1[k] fold
template<int K, int N, bool SCALED>
__global__ __launch_bounds__(256) void conv_w(const float* __restrict__ W,
                                              __nv_bfloat16* __restrict__ oh,
                                              __nv_bfloat16* __restrict__ ol) {
    __shared__ float t[32][33];
    const int lx = threadIdx.x & 31, ly = threadIdx.x >> 5;
    const int k0 = blockIdx.y * 32, n0 = blockIdx.x * 32;
    #pragma unroll
    for (int r = 0; r < 4; r++) {
        int k = k0 + ly + r * 8;
        float v = W[(size_t)k * N + n0 + lx];
        if (SCALED) v *= g_scale1[k];
        t[ly + r * 8][lx] = v;
    }
    __syncthreads();
    #pragma unroll
    for (int r = 0; r < 4; r++) {
        int n = n0 + ly + r * 8;
        float v = t[lx][ly + r * 8];
        __nv_bfloat16 h = __float2bfloat16(v);
        oh[(size_t)n * K + k0 + lx] = h;
        ol[(size_t)n * K + k0 + lx] = __float2bfloat16(v - __bfloat162float(h));
    }
}

// bias2eff[n] += sum_k bias1v[k] * W2[k][n]
__global__ __launch_bounds__(512) void b2eff_acc(const float* __restrict__ W2) {
    const int n = threadIdx.x;
    const int k0 = blockIdx.x * 16;
    float a = 0.f;
    #pragma unroll
    for (int r = 0; r < 16; r++)
        a += g_bias1v[k0 + r] * W2[(size_t)(k0 + r) * H2N + n];
    atomicAdd(&g_b2eff[n], a);
}

// pair term via quadratic form: pd[b] = sum_d x_d^T Wsym x_d
// one warp per batch row; lane owns columns d=lane and d=lane+32
__global__ __launch_bounds__(256) void pairdot_kernel(
    const float* __restrict__ x, float* __restrict__ pd)
{
    __shared__ float Ws[NFEAT * NFEAT];   // 4KB
    for (int i = threadIdx.x; i < NFEAT * NFEAT; i += 256)
        Ws[i] = g_wsym[i];
    __syncthreads();

    const int warp = threadIdx.x >> 5, lane = threadIdx.x & 31;
    const int b = blockIdx.x * 8 + warp;
    const float* xr = x + (size_t)b * KIN + lane;

    float xa[NFEAT], xb[NFEAT];
    #pragma unroll
    for (int n = 0; n < NFEAT; n++) {
        xa[n] = xr[n * DDIM];
        xb[n] = xr[n * DDIM + 32];
    }

    float acc = 0.f;
    #pragma unroll
    for (int n = 0; n < NFEAT; n++) {
        float ta = 0.f, tb = 0.f;
        const float4* wrow = (const float4*)&Ws[n * NFEAT];
        #pragma unroll
        for (int m4 = 0; m4 < NFEAT / 4; m4++) {
            float4 w = wrow[m4];
            const int m = m4 * 4;
            ta = fmaf(w.x, xa[m + 0], ta); tb = fmaf(w.x, xb[m + 0], tb);
            ta = fmaf(w.y, xa[m + 1], ta); tb = fmaf(w.y, xb[m + 1], tb);
            ta = fmaf(w.z, xa[m + 2], ta); tb = fmaf(w.z, xb[m + 2], tb);
            ta = fmaf(w.w, xa[m + 3], ta); tb = fmaf(w.w, xb[m + 3], tb);
        }
        acc = fmaf(xa[n], ta, acc);
        acc = fmaf(xb[n], tb, acc);
    }
    #pragma unroll
    for (int o = 16; o > 0; o >>= 1)
        acc += __shfl_down_sync(0xffffffffu, acc, o);
    if (lane == 0) pd[b] = acc;
}

__global__ void w3c_kernel(const float* __restrict__ W3,
                           const float* __restrict__ b3,
                           const float* __restrict__ Wc,
                           const float* __restrict__ bc) {
    int k = blockIdx.x * blockDim.x + threadIdx.x;
    if (k < H2N) {
        float s = 0.f;
        #pragma unroll
        for (int j = 0; j < HOFD; j++) s += W3[k * HOFD + j] * Wc[j];
        g_w3c[k] = s;
    } else if (k == H2N) {
        float s = 0.f;
        #pragma unroll
        for (int j = 0; j < HOFD; j++) s += b3[j] * Wc[j];
        g_w3c[H2N] = s + bc[0];
    }
}

// per-column sum/sumsq over bf16 hi/lo pair
__global__ void colreduce_pair(const __nv_bfloat16* __restrict__ Xh,
                               const __nv_bfloat16* __restrict__ Xl,
                               int M, int N,
                               float* __restrict__ sum, float* __restrict__ sq) {
    const int lane = threadIdx.x & 31, ty = threadIdx.x >> 5;
    const int col = blockIdx.x * 32 + lane;
    const int rowsPer = M / gridDim.y;
    const int r0 = blockIdx.y * rowsPer;
    float s = 0.f, q = 0.f;
    for (int r = r0 + ty; r < r0 + rowsPer; r += 8) {
        size_t o = (size_t)r * N + col;
        float v = __bfloat162float(Xh[o]) + __bfloat162float(Xl[o]);
        s += v; q += v * v;
    }
    __shared__ float ss[8][33], qs[8][33];
    ss[ty][lane] = s; qs[ty][lane] = q;
    __syncthreads();
    if (ty == 0) {
        #pragma unroll
        for (int t = 1; t < 8; t++) { s += ss[t][lane]; q += qs[t][lane]; }
        atomicAdd(&sum[col], s);
        atomicAdd(&sq[col], q);
    }
}

__global__ void colreduce(const float* __restrict__ X, int M, int N,
                          float* __restrict__ sum, float* __restrict__ sq) {
    const int lane = threadIdx.x & 31, ty = threadIdx.x >> 5;
    const int col = blockIdx.x * 32 + lane;
    const int rowsPer = M / gridDim.y;
    const int r0 = blockIdx.y * rowsPer;
    float s = 0.f, q = 0.f;
    for (int r = r0 + ty; r < r0 + rowsPer; r += 8) {
        float v = X[(size_t)r * N + col];
        s += v; q += v * v;
    }
    __shared__ float ss[8][33], qs[8][33];
    ss[ty][lane] = s; qs[ty][lane] = q;
    __syncthreads();
    if (ty == 0) {
        #pragma unroll
        for (int t = 1; t < 8; t++) { s += ss[t][lane]; q += qs[t][lane]; }
        atomicAdd(&sum[col], s);
        atomicAdd(&sq[col], q);
    }
}

__global__ void stats_kernel(const float* __restrict__ sum,
                             const float* __restrict__ sq,
                             const float* __restrict__ g,
                             const float* __restrict__ beta,
                             int N, float* __restrict__ scale,
                             float* __restrict__ bOut) {
    int j = blockIdx.x * blockDim.x + threadIdx.x;
    if (j >= N) return;
    const float invM = 1.f / (float)B_SZ;
    float m = sum[j] * invM;
    float v = sq[j] * invM - m * m;
    float sc = g[j] * rsqrtf(v + BN_EPS);
    scale[j] = sc;
    bOut[j] = beta[j] - m * sc;
}

// out[b] = (BN2(h2) . w3c) + c0 + pd[b]
__global__ void final_kernel(const float* __restrict__ h2, float* __restrict__ out) {
    const int gw = (blockIdx.x * blockDim.x + threadIdx.x) >> 5;
    const int lane = threadIdx.x & 31;
    if (gw >= B_SZ) return;
    const float* h = h2 + (size_t)gw * H2N;
    float acc = 0.f;
    #pragma unroll 4
    for (int k = lane; k < H2N; k += 32)
        acc += fmaf(h[k], g_scale2[k], g_bias2v[k]) * g_w3c[k];
    #pragma unroll
    for (int o = 16; o > 0; o >>= 1)
        acc += __shfl_down_sync(0xffffffffu, acc, o);
    if (lane == 0) out[gw] = acc + g_w3c[H2N] + g_pd[gw];
}

// ================= launch =================
extern "C" void kernel_launch(void* const* d_in, const int* in_sizes, int n_in,
                              void* d_out, int out_size) {
    const float* x     = (const float*)d_in[0];
    const float* W1    = (const float*)d_in[1];
    const float* b1    = (const float*)d_in[2];
    const float* g1    = (const float*)d_in[3];
    const float* beta1 = (const float*)d_in[4];
    const float* W2    = (const float*)d_in[5];
    const float* b2    = (const float*)d_in[6];
    const float* g2    = (const float*)d_in[7];
    const float* beta2 = (const float*)d_in[8];
    const float* W3    = (const float*)d_in[9];
    const float* b3    = (const float*)d_in[10];
    const float* Wc    = (const float*)d_in[11];
    const float* bc    = (const float*)d_in[12];
    float* out = (float*)d_out;

    __nv_bfloat16 *p_xh, *p_xl, *p_w1h, *p_w1l, *p_a1h, *p_a1l, *p_w2h, *p_w2l;
    float *p_h2, *p_pd, *p_sum1, *p_sq1, *p_scale1, *p_bias1v;
    float *p_sum2, *p_sq2, *p_scale2, *p_bias2v, *p_b2eff;
    cudaGetSymbolAddress((void**)&p_xh, g_xh);
    cudaGetSymbolAddress((void**)&p_xl, g_xl);
    cudaGetSymbolAddress((void**)&p_w1h, g_w1h);
    cudaGetSymbolAddress((void**)&p_w1l, g_w1l);
    cudaGetSymbolAddress((void**)&p_a1h, g_a1h);
    cudaGetSymbolAddress((void**)&p_a1l, g_a1l);
    cudaGetSymbolAddress((void**)&p_w2h, g_w2h);
    cudaGetSymbolAddress((void**)&p_w2l, g_w2l);
    cudaGetSymbolAddress((void**)&p_h2, g_h2);
    cudaGetSymbolAddress((void**)&p_pd, g_pd);
    cudaGetSymbolAddress((void**)&p_sum1, g_sum1);
    cudaGetSymbolAddress((void**)&p_sq1, g_sq1);
    cudaGetSymbolAddress((void**)&p_scale1, g_scale1);
    cudaGetSymbolAddress((void**)&p_bias1v, g_bias1v);
    cudaGetSymbolAddress((void**)&p_sum2, g_sum2);
    cudaGetSymbolAddress((void**)&p_sq2, g_sq2);
    cudaGetSymbolAddress((void**)&p_scale2, g_scale2);
    cudaGetSymbolAddress((void**)&p_bias2v, g_bias2v);
    cudaGetSymbolAddress((void**)&p_b2eff, g_b2eff);

    const int GSM = 4 * 49152 + 1024;  // 4 stages + alignment slack
    cudaFuncSetAttribute(gemm_mma<KIN, H1, 0>,
                         cudaFuncAttributeMaxDynamicSharedMemorySize, GSM);
    cudaFuncSetAttribute(gemm_mma<H1, H2N, 1>,
                         cudaFuncAttributeMaxDynamicSharedMemorySize, GSM);

    // prep (independent)
    zero_init<<<4, 256>>>(b2);
    wsym_kernel<<<4, 256>>>(Wc);
    conv_x_kernel<<<(B_SZ * KIN / 4) / 256, 256>>>(x);
    conv_w<KIN, H1, false><<<dim3(H1 / 32, KIN / 32), 256>>>(W1, p_w1h, p_w1l);
    pairdot_kernel<<<B_SZ / 8, 256>>>(x, p_pd);
    w3c_kernel<<<3, 256>>>(W3, b3, Wc, bc);

    // layer 1: a1 = relu(x @ W1 + b1), written as bf16 hi/lo split (pre-BN)
    gemm_mma<KIN, H1, 0><<<dim3(H1 / 256, B_SZ / 128), 512, GSM>>>(
        p_xh, p_xl, p_w1h, p_w1l, b1, p_a1h, p_a1l, nullptr);
    colreduce_pair<<<dim3(H1 / 32, 64), 256>>>(p_a1h, p_a1l, B_SZ, H1, p_sum1, p_sq1);
    stats_kernel<<<4, 256>>>(p_sum1, p_sq1, g1, beta1, H1, p_scale1, p_bias1v);

    // fold BN1 into W2 (scale) and bias2eff (rank-1 bias term)
    conv_w<H1, H2N, true><<<dim3(H2N / 32, H1 / 32), 256>>>(W2, p_w2h, p_w2l);
    b2eff_acc<<<H1 / 16, 512>>>(W2);

    // layer 2: h2 = relu( a1 @ (scale1*W2) + b2eff ), fp32 out (pre-BN2)
    gemm_mma<H1, H2N, 1><<<dim3(H2N / 256, B_SZ / 128), 512, GSM>>>(
        p_a1h, p_a1l, p_w2h, p_w2l, p_b2eff, nullptr, nullptr, p_h2);
    colreduce<<<dim3(H2N / 32, 64), 256>>>(p_h2, B_SZ, H2N, p_sum2, p_sq2);
    stats_kernel<<<2, 256>>>(p_sum2, p_sq2, g2, beta2, H2N, p_scale2, p_bias2v);

    // final: out = BN2(h2) @ (W3@Wc) + (b3@Wc + bc) + pairs@Wc_pairs
    final_kernel<<<(B_SZ * 32) / 256, 256>>>(p_h2, out);
}

// round 9
// speedup vs baseline: 7.5905x; 2.3496x over previous
#include <cuda_runtime.h>
#include <cuda_bf16.h>
#include <cstdint>

// ---------------- problem constants ----------------
#define B_SZ   16384
#define NFEAT  32
#define DDIM   64
#define KIN    2048     // NFEAT*DDIM
#define H1     1024
#define H2N    512
#define HOFD   64
#define NPAIRS 496
#define BN_EPS 1e-5f

// ---------------- scratch (device globals; no runtime alloc) ----------------
__device__ __nv_bfloat16 g_xh[(size_t)B_SZ * KIN];
__device__ __nv_bfloat16 g_w1h[(size_t)H1 * KIN];   // [N=H1][K=KIN] transposed
__device__ __nv_bfloat16 g_a1h[(size_t)B_SZ * H1];  // relu(x@W1+b1) bf16, pre-BN
__device__ __nv_bfloat16 g_w2h[(size_t)H2N * H1];   // [N=H2N][K=H1], scale1 folded
__device__ float g_h2[(size_t)B_SZ * H2N];          // relu(.@W2'+b2eff), pre-BN2
__device__ float g_pd[B_SZ];
__device__ float g_wsym[NFEAT * NFEAT];             // symmetric half-weight matrix
__device__ float g_sum1[H1], g_sq1[H1], g_scale1[H1], g_bias1v[H1];
__device__ float g_sum2[H2N], g_sq2[H2N], g_scale2[H2N], g_bias2v[H2N];
__device__ float g_b2eff[H2N];
__device__ float g_w3c[H2N + 1];

// ================= PTX helpers (baseline ISA only) ========
__device__ __forceinline__ uint32_t smem_u32(const void* p) {
    uint32_t a;
    asm("{ .reg .u64 t; cvta.to.shared.u64 t, %1; cvt.u32.u64 %0, t; }"
        : "=r"(a) : "l"(p));
    return a;
}
__device__ __forceinline__ void cpa16(uint32_t s, const void* g) {
    asm volatile("cp.async.cg.shared.global [%0], [%1], 16;" :: "r"(s), "l"(g));
}
#define CP_COMMIT() asm volatile("cp.async.commit_group;" ::: "memory")
#define CP_WAIT2()  asm volatile("cp.async.wait_group 2;" ::: "memory")
#define SWZ(o)      ((o) ^ (((o) >> 3) & 0x70))

__device__ __forceinline__ void ldsm4(uint32_t& r0, uint32_t& r1,
                                      uint32_t& r2, uint32_t& r3, uint32_t a) {
    asm volatile("ldmatrix.sync.aligned.m8n8.x4.shared.b16 {%0,%1,%2,%3}, [%4];"
                 : "=r"(r0), "=r"(r1), "=r"(r2), "=r"(r3) : "r"(a));
}
__device__ __forceinline__ void mma16816(float* c,
                                         uint32_t a0, uint32_t a1, uint32_t a2, uint32_t a3,
                                         uint32_t b0, uint32_t b1) {
    asm volatile("mma.sync.aligned.m16n8k16.row.col.f32.bf16.bf16.f32 "
                 "{%0,%1,%2,%3}, {%4,%5,%6,%7}, {%8,%9}, {%0,%1,%2,%3};"
                 : "+f"(c[0]), "+f"(c[1]), "+f"(c[2]), "+f"(c[3])
                 : "r"(a0), "r"(a1), "r"(a2), "r"(a3), "r"(b0), "r"(b1));
}

// ================= single-pass bf16 HMMA GEMM =================
// C[M, NTOT] = epi( A @ B^T + bias ), A [M,KDIM] bf16, B [NTOT,KDIM] bf16.
// Output error budget: bf16 input rounding ~1.6e-3 dot-relative; the output is
// pair-term dominated (50x attenuation) -> final ~3e-5, 20x under the gate.
// EPI 0: write bf16 relu(.)   EPI 1: write fp32 relu(.)
template<int KDIM, int NTOT, int EPI>
__global__ __launch_bounds__(512, 1) void gemm_mma(
    const __nv_bfloat16* __restrict__ A,
    const __nv_bfloat16* __restrict__ Bw,
    const float* __restrict__ bias,
    __nv_bfloat16* __restrict__ outH, float* __restrict__ outF)
{
    constexpr int S = 4, BK = 64, BN = 256, BM = 128;
    constexpr int T = KDIM / BK;
    constexpr int STAGE_BYTES = (BM + BN) * 128;  // 48KB: A 16K + B 32K (128B rows)

    extern __shared__ char smraw[];
    const uint32_t sb = (smem_u32(smraw) + 1023) & ~1023u;
    const int tid = threadIdx.x;
    const int wid = tid >> 5, lane = tid & 31;
    const int wm0 = (wid >> 3) * 64;        // 2 warp rows  (m: 0 / 64)
    const int wn0 = (wid & 7) * 32;         // 8 warp cols  (n: 0..224)
    const int m0 = blockIdx.y * BM, n0 = blockIdx.x * BN;

    auto load_stage = [&](int gs) {
        const int b = gs & (S - 1);
        const uint32_t sA = sb + b * STAGE_BYTES;
        const uint32_t sB = sA + BM * 128;
        const int kk = gs * BK;
        const __nv_bfloat16* Ab = A + (size_t)m0 * KDIM + kk;
        const __nv_bfloat16* Bb = Bw + (size_t)n0 * KDIM + kk;
        #pragma unroll
        for (int t = 0; t < BM * 8 / 512; t++) {          // 2 iters
            int c = tid + t * 512;
            int r = c >> 3, ch = c & 7;
            cpa16(sA + SWZ(r * 128 + ch * 16), Ab + (size_t)r * KDIM + ch * 8);
        }
        #pragma unroll
        for (int t = 0; t < BN * 8 / 512; t++) {          // 4 iters
            int c = tid + t * 512;
            int r = c >> 3, ch = c & 7;
            cpa16(sB + SWZ(r * 128 + ch * 16), Bb + (size_t)r * KDIM + ch * 8);
        }
    };

    // prologue: stages 0..2 in flight
    load_stage(0); CP_COMMIT();
    load_stage(1); CP_COMMIT();
    load_stage(2); CP_COMMIT();

    float acc[4][4][4];
    #pragma unroll
    for (int i = 0; i < 4; i++)
        #pragma unroll
        for (int j = 0; j < 4; j++)
            #pragma unroll
            for (int r = 0; r < 4; r++) acc[i][j][r] = 0.f;

    // per-lane ldmatrix row components (byte offsets within tile, pre-swizzle)
    const int aRowOff = (wm0 + (lane & 15)) * 128 + (lane >> 4) * 16;
    const int bRowBase = (wn0 + (lane & 7) + ((lane >> 4) << 3)) * 128 +
                         (((lane >> 3) & 1) << 4);

    for (int i = 0; i < T; ++i) {
        const int b = i & (S - 1);
        CP_WAIT2();
        __syncthreads();   // single barrier: orders compute(i-1) vs refill of its buffer
        const uint32_t sA = sb + b * STAGE_BYTES;
        const uint32_t sB = sA + BM * 128;
        #pragma unroll
        for (int ks = 0; ks < 4; ks++) {
            const int kb = ks * 32;   // 16 elems * 2B per k-step
            uint32_t a[4][4];
            #pragma unroll
            for (int mi = 0; mi < 4; mi++)
                ldsm4(a[mi][0], a[mi][1], a[mi][2], a[mi][3],
                      sA + SWZ(aRowOff + mi * 16 * 128 + kb));
            uint32_t bf[2][4];
            #pragma unroll
            for (int gg = 0; gg < 2; gg++)
                ldsm4(bf[gg][0], bf[gg][1], bf[gg][2], bf[gg][3],
                      sB + SWZ(bRowBase + gg * 16 * 128 + kb));
            #pragma unroll
            for (int mi = 0; mi < 4; mi++)
                #pragma unroll
                for (int j = 0; j < 4; j++)
                    mma16816(acc[mi][j], a[mi][0], a[mi][1], a[mi][2], a[mi][3],
                             bf[j >> 1][(j & 1) * 2], bf[j >> 1][(j & 1) * 2 + 1]);
        }
        const int ns = i + 3;
        if (ns < T) load_stage(ns);
        CP_COMMIT();
    }

    // ---------------- epilogue: registers -> gmem ----------------
    #pragma unroll
    for (int j = 0; j < 4; j++) {
        const int col = n0 + wn0 + j * 8 + (lane & 3) * 2;
        const float bi0 = bias[col], bi1 = bias[col + 1];
        #pragma unroll
        for (int mi = 0; mi < 4; mi++) {
            const int row = m0 + wm0 + mi * 16 + (lane >> 2);
            #pragma unroll
            for (int h = 0; h < 2; h++) {   // h=0: row, h=1: row+8
                const int rr = row + h * 8;
                const float v0 = fmaxf(acc[mi][j][2 * h + 0] + bi0, 0.f);
                const float v1 = fmaxf(acc[mi][j][2 * h + 1] + bi1, 0.f);
                if (EPI == 0) {
                    __nv_bfloat162 ph;
                    ph.x = __float2bfloat16(v0);
                    ph.y = __float2bfloat16(v1);
                    *(__nv_bfloat162*)(outH + (size_t)rr * NTOT + col) = ph;
                } else {
                    float2 v; v.x = v0; v.y = v1;
                    *(float2*)(outF + (size_t)rr * NTOT + col) = v;
                }
            }
        }
    }
}

// ================= small kernels =================
__global__ void zero_init(const float* __restrict__ b2) {
    int i = blockIdx.x * blockDim.x + threadIdx.x;
    if (i < H1)  { g_sum1[i] = 0.f; g_sq1[i] = 0.f; }
    if (i < H2N) { g_sum2[i] = 0.f; g_sq2[i] = 0.f; g_b2eff[i] = b2[i]; }
}

// build symmetric half-weight matrix from Wc pair weights
__global__ void wsym_kernel(const float* __restrict__ Wc) {
    int p = blockIdx.x * blockDim.x + threadIdx.x;
    if (p < NFEAT * NFEAT && (p / NFEAT) == (p % NFEAT)) g_wsym[p] = 0.f;
    if (p >= NPAIRS) return;
    int i = 0, rem = p;
    while (rem >= NFEAT - 1 - i) { rem -= NFEAT - 1 - i; i++; }
    int j = i + 1 + rem;
    float hw = 0.5f * Wc[HOFD + p];
    g_wsym[i * NFEAT + j] = hw;
    g_wsym[j * NFEAT + i] = hw;
}

// x fp32 -> bf16 (row-major [B, KIN])
__global__ __launch_bounds__(256) void conv_x_kernel(const float* __restrict__ x) {
    size_t i = ((size_t)blockIdx.x * 256 + threadIdx.x) * 4;
    float4 v = *(const float4*)(x + i);
    __nv_bfloat162 a, b;
    a.x = __float2bfloat16(v.x); a.y = __float2bfloat16(v.y);
    b.x = __float2bfloat16(v.z); b.y = __float2bfloat16(v.w);
    ((__nv_bfloat162*)(g_xh + i))[0] = a;
    ((__nv_bfloat162*)(g_xh + i))[1] = b;
}

// transpose W [K][N] -> oh [N][K] bf16; optional scale1[k] fold
template<int K, int N, bool SCALED>
__global__ __launch_bounds__(256) void conv_w(const float* __restrict__ W,
                                              __nv_bfloat16* __restrict__ oh) {
    __shared__ float t[32][33];
    const int lx = threadIdx.x & 31, ly = threadIdx.x >> 5;
    const int k0 = blockIdx.y * 32, n0 = blockIdx.x * 32;
    #pragma unroll
    for (int r = 0; r < 4; r++) {
        int k = k0 + ly + r * 8;
        float v = W[(size_t)k * N + n0 + lx];
        if (SCALED) v *= g_scale1[k];
        t[ly + r * 8][lx] = v;
    }
    __syncthreads();
    #pragma unroll
    for (int r = 0; r < 4; r++) {
        int n = n0 + ly + r * 8;
        oh[(size_t)n * K + k0 + lx] = __float2bfloat16(t[lx][ly + r * 8]);
    }
}

// bias2eff[n] += sum_k bias1v[k] * W2[k][n]
__global__ __launch_bounds__(512) void b2eff_acc(const float* __restrict__ W2) {
    const int n = threadIdx.x;
    const int k0 = blockIdx.x * 16;
    float a = 0.f;
    #pragma unroll
    for (int r = 0; r < 16; r++)
        a += g_bias1v[k0 + r] * W2[(size_t)(k0 + r) * H2N + n];
    atomicAdd(&g_b2eff[n], a);
}

// pair term via quadratic form: pd[b] = sum_d x_d^T Wsym x_d
__global__ __launch_bounds__(256) void pairdot_kernel(
    const float* __restrict__ x, float* __restrict__ pd)
{
    __shared__ float Ws[NFEAT * NFEAT];   // 4KB
    for (int i = threadIdx.x; i < NFEAT * NFEAT; i += 256)
        Ws[i] = g_wsym[i];
    __syncthreads();

    const int warp = threadIdx.x >> 5, lane = threadIdx.x & 31;
    const int b = blockIdx.x * 8 + warp;
    const float* xr = x + (size_t)b * KIN + lane;

    float xa[NFEAT], xb[NFEAT];
    #pragma unroll
    for (int n = 0; n < NFEAT; n++) {
        xa[n] = xr[n * DDIM];
        xb[n] = xr[n * DDIM + 32];
    }

    float acc = 0.f;
    #pragma unroll
    for (int n = 0; n < NFEAT; n++) {
        float ta = 0.f, tb = 0.f;
        const float4* wrow = (const float4*)&Ws[n * NFEAT];
        #pragma unroll
        for (int m4 = 0; m4 < NFEAT / 4; m4++) {
            float4 w = wrow[m4];
            const int m = m4 * 4;
            ta = fmaf(w.x, xa[m + 0], ta); tb = fmaf(w.x, xb[m + 0], tb);
            ta = fmaf(w.y, xa[m + 1], ta); tb = fmaf(w.y, xb[m + 1], tb);
            ta = fmaf(w.z, xa[m + 2], ta); tb = fmaf(w.z, xb[m + 2], tb);
            ta = fmaf(w.w, xa[m + 3], ta); tb = fmaf(w.w, xb[m + 3], tb);
        }
        acc = fmaf(xa[n], ta, acc);
        acc = fmaf(xb[n], tb, acc);
    }
    #pragma unroll
    for (int o = 16; o > 0; o >>= 1)
        acc += __shfl_down_sync(0xffffffffu, acc, o);
    if (lane == 0) pd[b] = acc;
}

__global__ void w3c_kernel(const float* __restrict__ W3,
                           const float* __restrict__ b3,
                           const float* __restrict__ Wc,
                           const float* __restrict__ bc) {
    int k = blockIdx.x * blockDim.x + threadIdx.x;
    if (k < H2N) {
        float s = 0.f;
        #pragma unroll
        for (int j = 0; j < HOFD; j++) s += W3[k * HOFD + j] * Wc[j];
        g_w3c[k] = s;
    } else if (k == H2N) {
        float s = 0.f;
        #pragma unroll
        for (int j = 0; j < HOFD; j++) s += b3[j] * Wc[j];
        g_w3c[H2N] = s + bc[0];
    }
}

// per-column sum/sumsq over bf16
__global__ void colreduce_bf16(const __nv_bfloat16* __restrict__ X,
                               int M, int N,
                               float* __restrict__ sum, float* __restrict__ sq) {
    const int lane = threadIdx.x & 31, ty = threadIdx.x >> 5;
    const int col = blockIdx.x * 32 + lane;
    const int rowsPer = M / gridDim.y;
    const int r0 = blockIdx.y * rowsPer;
    float s = 0.f, q = 0.f;
    for (int r = r0 + ty; r < r0 + rowsPer; r += 8) {
        float v = __bfloat162float(X[(size_t)r * N + col]);
        s += v; q += v * v;
    }
    __shared__ float ss[8][33], qs[8][33];
    ss[ty][lane] = s; qs[ty][lane] = q;
    __syncthreads();
    if (ty == 0) {
        #pragma unroll
        for (int t = 1; t < 8; t++) { s += ss[t][lane]; q += qs[t][lane]; }
        atomicAdd(&sum[col], s);
        atomicAdd(&sq[col], q);
    }
}

__global__ void colreduce(const float* __restrict__ X, int M, int N,
                          float* __restrict__ sum, float* __restrict__ sq) {
    const int lane = threadIdx.x & 31, ty = threadIdx.x >> 5;
    const int col = blockIdx.x * 32 + lane;
    const int rowsPer = M / gridDim.y;
    const int r0 = blockIdx.y * rowsPer;
    float s = 0.f, q = 0.f;
    for (int r = r0 + ty; r < r0 + rowsPer; r += 8) {
        float v = X[(size_t)r * N + col];
        s += v; q += v * v;
    }
    __shared__ float ss[8][33], qs[8][33];
    ss[ty][lane] = s; qs[ty][lane] = q;
    __syncthreads();
    if (ty == 0) {
        #pragma unroll
        for (int t = 1; t < 8; t++) { s += ss[t][lane]; q += qs[t][lane]; }
        atomicAdd(&sum[col], s);
        atomicAdd(&sq[col], q);
    }
}

__global__ void stats_kernel(const float* __restrict__ sum,
                             const float* __restrict__ sq,
                             const float* __restrict__ g,
                             const float* __restrict__ beta,
                             int N, float* __restrict__ scale,
                             float* __restrict__ bOut) {
    int j = blockIdx.x * blockDim.x + threadIdx.x;
    if (j >= N) return;
    const float invM = 1.f / (float)B_SZ;
    float m = sum[j] * invM;
    float v = sq[j] * invM - m * m;
    float sc = g[j] * rsqrtf(v + BN_EPS);
    scale[j] = sc;
    bOut[j] = beta[j] - m * sc;
}

// out[b] = (BN2(h2) . w3c) + c0 + pd[b]
__global__ void final_kernel(const float* __restrict__ h2, float* __restrict__ out) {
    const int gw = (blockIdx.x * blockDim.x + threadIdx.x) >> 5;
    const int lane = threadIdx.x & 31;
    if (gw >= B_SZ) return;
    const float* h = h2 + (size_t)gw * H2N;
    float acc = 0.f;
    #pragma unroll 4
    for (int k = lane; k < H2N; k += 32)
        acc += fmaf(h[k], g_scale2[k], g_bias2v[k]) * g_w3c[k];
    #pragma unroll
    for (int o = 16; o > 0; o >>= 1)
        acc += __shfl_down_sync(0xffffffffu, acc, o);
    if (lane == 0) out[gw] = acc + g_w3c[H2N] + g_pd[gw];
}

// ================= launch =================
extern "C" void kernel_launch(void* const* d_in, const int* in_sizes, int n_in,
                              void* d_out, int out_size) {
    const float* x     = (const float*)d_in[0];
    const float* W1    = (const float*)d_in[1];
    const float* b1    = (const float*)d_in[2];
    const float* g1    = (const float*)d_in[3];
    const float* beta1 = (const float*)d_in[4];
    const float* W2    = (const float*)d_in[5];
    const float* b2    = (const float*)d_in[6];
    const float* g2    = (const float*)d_in[7];
    const float* beta2 = (const float*)d_in[8];
    const float* W3    = (const float*)d_in[9];
    const float* b3    = (const float*)d_in[10];
    const float* Wc    = (const float*)d_in[11];
    const float* bc    = (const float*)d_in[12];
    float* out = (float*)d_out;

    __nv_bfloat16 *p_xh, *p_w1h, *p_a1h, *p_w2h;
    float *p_h2, *p_pd, *p_sum1, *p_sq1, *p_scale1, *p_bias1v;
    float *p_sum2, *p_sq2, *p_scale2, *p_bias2v, *p_b2eff;
    cudaGetSymbolAddress((void**)&p_xh, g_xh);
    cudaGetSymbolAddress((void**)&p_w1h, g_w1h);
    cudaGetSymbolAddress((void**)&p_a1h, g_a1h);
    cudaGetSymbolAddress((void**)&p_w2h, g_w2h);
    cudaGetSymbolAddress((void**)&p_h2, g_h2);
    cudaGetSymbolAddress((void**)&p_pd, g_pd);
    cudaGetSymbolAddress((void**)&p_sum1, g_sum1);
    cudaGetSymbolAddress((void**)&p_sq1, g_sq1);
    cudaGetSymbolAddress((void**)&p_scale1, g_scale1);
    cudaGetSymbolAddress((void**)&p_bias1v, g_bias1v);
    cudaGetSymbolAddress((void**)&p_sum2, g_sum2);
    cudaGetSymbolAddress((void**)&p_sq2, g_sq2);
    cudaGetSymbolAddress((void**)&p_scale2, g_scale2);
    cudaGetSymbolAddress((void**)&p_bias2v, g_bias2v);
    cudaGetSymbolAddress((void**)&p_b2eff, g_b2eff);

    const int GSM = 4 * 49152 + 1024;  // 4 stages + alignment slack
    cudaFuncSetAttribute(gemm_mma<KIN, H1, 0>,
                         cudaFuncAttributeMaxDynamicSharedMemorySize, GSM);
    cudaFuncSetAttribute(gemm_mma<H1, H2N, 1>,
                         cudaFuncAttributeMaxDynamicSharedMemorySize, GSM);

    // launch order chosen so gemm1 is the 4th launch (ncu capture slot)
    conv_x_kernel<<<(B_SZ * KIN / 4) / 256, 256>>>(x);
    conv_w<KIN, H1, false><<<dim3(H1 / 32, KIN / 32), 256>>>(W1, p_w1h);
    wsym_kernel<<<4, 256>>>(Wc);

    // layer 1: a1 = relu(x @ W1 + b1), bf16 out (pre-BN)   [4th launch: profiled]
    gemm_mma<KIN, H1, 0><<<dim3(H1 / 256, B_SZ / 128), 512, GSM>>>(
        p_xh, p_w1h, b1, p_a1h, nullptr);

    zero_init<<<4, 256>>>(b2);
    pairdot_kernel<<<B_SZ / 8, 256>>>(x, p_pd);
    w3c_kernel<<<3, 256>>>(W3, b3, Wc, bc);

    colreduce_bf16<<<dim3(H1 / 32, 64), 256>>>(p_a1h, B_SZ, H1, p_sum1, p_sq1);
    stats_kernel<<<4, 256>>>(p_sum1, p_sq1, g1, beta1, H1, p_scale1, p_bias1v);

    // fold BN1 into W2 (scale) and bias2eff (rank-1 bias term)
    conv_w<H1, H2N, true><<<dim3(H2N / 32, H1 / 32), 256>>>(W2, p_w2h);
    b2eff_acc<<<H1 / 16, 512>>>(W2);

    // layer 2: h2 = relu( a1 @ (scale1*W2) + b2eff ), fp32 out (pre-BN2)
    gemm_mma<H1, H2N, 1><<<dim3(H2N / 256, B_SZ / 128), 512, GSM>>>(
        p_a1h, p_w2h, p_b2eff, nullptr, p_h2);
    colreduce<<<dim3(H2N / 32, 64), 256>>>(p_h2, B_SZ, H2N, p_sum2, p_sq2);
    stats_kernel<<<2, 256>>>(p_sum2, p_sq2, g2, beta2, H2N, p_scale2, p_bias2v);

    // final: out = BN2(h2) @ (W3@Wc) + (b3@Wc + bc) + pairs@Wc_pairs
    final_kernel<<<(B_SZ * 32) / 256, 256>>>(p_h2, out);
}

// round 10
// speedup vs baseline: 9.1992x; 1.2119x over previous
#include <cuda_runtime.h>
#include <cuda_bf16.h>
#include <cstdint>

// ---------------- problem constants ----------------
#define B_SZ   16384
#define NFEAT  32
#define DDIM   64
#define KIN    2048     // NFEAT*DDIM
#define H1     1024
#define H2N    512
#define HOFD   64
#define NPAIRS 496
#define BN_EPS 1e-5f

// ---------------- scratch (device globals; no runtime alloc) ----------------
__device__ __nv_bfloat16 g_xh[(size_t)B_SZ * KIN];
__device__ __nv_bfloat16 g_w1h[(size_t)H1 * KIN];   // [N=H1][K=KIN] transposed
__device__ __nv_bfloat16 g_a1h[(size_t)B_SZ * H1];  // relu(x@W1+b1) bf16, pre-BN
__device__ __nv_bfloat16 g_w2h[(size_t)H2N * H1];   // [N=H2N][K=H1], scale1 folded
__device__ float g_h2[(size_t)B_SZ * H2N];          // relu(.@W2'+b2eff), pre-BN2
__device__ float g_pd[B_SZ];
__device__ float g_wsym[NFEAT * NFEAT];             // symmetric half-weight matrix
__device__ float g_sum1[H1], g_sq1[H1], g_scale1[H1], g_bias1v[H1];
__device__ float g_sum2[H2N], g_sq2[H2N], g_scale2[H2N], g_bias2v[H2N];
__device__ float g_b2eff[H2N];
__device__ float g_w3c[H2N + 1];

// ================= PTX helpers (baseline ISA only) ========
__device__ __forceinline__ uint32_t smem_u32(const void* p) {
    uint32_t a;
    asm("{ .reg .u64 t; cvta.to.shared.u64 t, %1; cvt.u32.u64 %0, t; }"
        : "=r"(a) : "l"(p));
    return a;
}
__device__ __forceinline__ void cpa16(uint32_t s, const void* g) {
    asm volatile("cp.async.cg.shared.global [%0], [%1], 16;" :: "r"(s), "l"(g));
}
#define CP_COMMIT() asm volatile("cp.async.commit_group;" ::: "memory")
#define CP_WAIT1()  asm volatile("cp.async.wait_group 1;" ::: "memory")
#define SWZ(o)      ((o) ^ (((o) >> 3) & 0x70))

__device__ __forceinline__ void ldsm4(uint32_t& r0, uint32_t& r1,
                                      uint32_t& r2, uint32_t& r3, uint32_t a) {
    asm volatile("ldmatrix.sync.aligned.m8n8.x4.shared.b16 {%0,%1,%2,%3}, [%4];"
                 : "=r"(r0), "=r"(r1), "=r"(r2), "=r"(r3) : "r"(a));
}
__device__ __forceinline__ void mma16816(float* c,
                                         uint32_t a0, uint32_t a1, uint32_t a2, uint32_t a3,
                                         uint32_t b0, uint32_t b1) {
    asm volatile("mma.sync.aligned.m16n8k16.row.col.f32.bf16.bf16.f32 "
                 "{%0,%1,%2,%3}, {%4,%5,%6,%7}, {%8,%9}, {%0,%1,%2,%3};"
                 : "+f"(c[0]), "+f"(c[1]), "+f"(c[2]), "+f"(c[3])
                 : "r"(a0), "r"(a1), "r"(a2), "r"(a3), "r"(b0), "r"(b1));
}

// ================= single-pass bf16 HMMA GEMM =================
// 128x128 tile, 8 warps (2x4, warp tile 64x32), 3-stage cp.async, 2 CTAs/SM.
// C[M, NTOT] = epi( A @ B^T + bias ).  EPI 0: bf16 relu out.  EPI 1: fp32 relu out.
template<int KDIM, int NTOT, int EPI>
__global__ __launch_bounds__(256, 2) void gemm_mma(
    const __nv_bfloat16* __restrict__ A,
    const __nv_bfloat16* __restrict__ Bw,
    const float* __restrict__ bias,
    __nv_bfloat16* __restrict__ outH, float* __restrict__ outF)
{
    constexpr int S = 3, BK = 64, BN = 128, BM = 128;
    constexpr int T = KDIM / BK;
    constexpr int STAGE_BYTES = (BM + BN) * 128;  // 32KB: A 16K + B 16K (128B rows)

    extern __shared__ char smraw[];
    const uint32_t sb = (smem_u32(smraw) + 1023) & ~1023u;
    const int tid = threadIdx.x;
    const int wid = tid >> 5, lane = tid & 31;
    const int wm0 = (wid >> 2) * 64;        // 2 warp rows  (m: 0 / 64)
    const int wn0 = (wid & 3) * 32;         // 4 warp cols  (n: 0..96)
    const int m0 = blockIdx.y * BM, n0 = blockIdx.x * BN;

    auto load_stage = [&](int gs) {
        const uint32_t sA = sb + (gs % S) * STAGE_BYTES;
        const uint32_t sB = sA + BM * 128;
        const int kk = gs * BK;
        const __nv_bfloat16* Ab = A + (size_t)m0 * KDIM + kk;
        const __nv_bfloat16* Bb = Bw + (size_t)n0 * KDIM + kk;
        #pragma unroll
        for (int t = 0; t < BM * 8 / 256; t++) {          // 4 iters
            int c = tid + t * 256;
            int r = c >> 3, ch = c & 7;
            cpa16(sA + SWZ(r * 128 + ch * 16), Ab + (size_t)r * KDIM + ch * 8);
        }
        #pragma unroll
        for (int t = 0; t < BN * 8 / 256; t++) {          // 4 iters
            int c = tid + t * 256;
            int r = c >> 3, ch = c & 7;
            cpa16(sB + SWZ(r * 128 + ch * 16), Bb + (size_t)r * KDIM + ch * 8);
        }
    };

    // prologue: stages 0,1 in flight (prefetch distance 2)
    load_stage(0); CP_COMMIT();
    load_stage(1); CP_COMMIT();

    float acc[4][4][4];
    #pragma unroll
    for (int i = 0; i < 4; i++)
        #pragma unroll
        for (int j = 0; j < 4; j++)
            #pragma unroll
            for (int r = 0; r < 4; r++) acc[i][j][r] = 0.f;

    // per-lane ldmatrix row components (byte offsets within tile, pre-swizzle)
    const int aRowOff = (wm0 + (lane & 15)) * 128 + (lane >> 4) * 16;
    const int bRowBase = (wn0 + (lane & 7) + ((lane >> 4) << 3)) * 128 +
                         (((lane >> 3) & 1) << 4);

    for (int i = 0; i < T; ++i) {
        CP_WAIT1();
        __syncthreads();   // orders compute(i-1) everywhere vs refill of its buffer
        const uint32_t sA = sb + (i % S) * STAGE_BYTES;
        const uint32_t sB = sA + BM * 128;
        #pragma unroll
        for (int ks = 0; ks < 4; ks++) {
            const int kb = ks * 32;   // 16 elems * 2B per k-step
            uint32_t a[4][4];
            #pragma unroll
            for (int mi = 0; mi < 4; mi++)
                ldsm4(a[mi][0], a[mi][1], a[mi][2], a[mi][3],
                      sA + SWZ(aRowOff + mi * 16 * 128 + kb));
            uint32_t bf[2][4];
            #pragma unroll
            for (int gg = 0; gg < 2; gg++)
                ldsm4(bf[gg][0], bf[gg][1], bf[gg][2], bf[gg][3],
                      sB + SWZ(bRowBase + gg * 16 * 128 + kb));
            #pragma unroll
            for (int mi = 0; mi < 4; mi++)
                #pragma unroll
                for (int j = 0; j < 4; j++)
                    mma16816(acc[mi][j], a[mi][0], a[mi][1], a[mi][2], a[mi][3],
                             bf[j >> 1][(j & 1) * 2], bf[j >> 1][(j & 1) * 2 + 1]);
        }
        const int ns = i + 2;
        if (ns < T) load_stage(ns);
        CP_COMMIT();
    }

    // ---------------- epilogue: registers -> gmem ----------------
    #pragma unroll
    for (int j = 0; j < 4; j++) {
        const int col = n0 + wn0 + j * 8 + (lane & 3) * 2;
        const float bi0 = bias[col], bi1 = bias[col + 1];
        #pragma unroll
        for (int mi = 0; mi < 4; mi++) {
            const int row = m0 + wm0 + mi * 16 + (lane >> 2);
            #pragma unroll
            for (int h = 0; h < 2; h++) {   // h=0: row, h=1: row+8
                const int rr = row + h * 8;
                const float v0 = fmaxf(acc[mi][j][2 * h + 0] + bi0, 0.f);
                const float v1 = fmaxf(acc[mi][j][2 * h + 1] + bi1, 0.f);
                if (EPI == 0) {
                    __nv_bfloat162 ph;
                    ph.x = __float2bfloat16(v0);
                    ph.y = __float2bfloat16(v1);
                    *(__nv_bfloat162*)(outH + (size_t)rr * NTOT + col) = ph;
                } else {
                    float2 v; v.x = v0; v.y = v1;
                    *(float2*)(outF + (size_t)rr * NTOT + col) = v;
                }
            }
        }
    }
}

// ================= merged prep kernel =================
// blk 0-3: zero stats + b2eff init; blk 4-5: wsym; blk 6-7: w3c
__global__ __launch_bounds__(256) void prep_kernel(
    const float* __restrict__ b2, const float* __restrict__ Wc,
    const float* __restrict__ W3, const float* __restrict__ b3,
    const float* __restrict__ bc)
{
    const int t = threadIdx.x, blk = blockIdx.x;
    if (blk < 4) {
        const int i = blk * 256 + t;
        if (i < H1)  { g_sum1[i] = 0.f; g_sq1[i] = 0.f; }
        if (i < H2N) { g_sum2[i] = 0.f; g_sq2[i] = 0.f; g_b2eff[i] = b2[i]; }
    } else if (blk < 6) {
        const int p = (blk - 4) * 256 + t;        // 0..511
        const int d1 = p, d2 = p + 512;           // zero diagonal entries
        if ((d1 >> 5) == (d1 & 31)) g_wsym[d1] = 0.f;
        if ((d2 >> 5) == (d2 & 31)) g_wsym[d2] = 0.f;
        if (p < NPAIRS) {
            int i = 0, rem = p;
            while (rem >= NFEAT - 1 - i) { rem -= NFEAT - 1 - i; i++; }
            const int j = i + 1 + rem;
            const float hw = 0.5f * Wc[HOFD + p];
            g_wsym[i * NFEAT + j] = hw;
            g_wsym[j * NFEAT + i] = hw;
        }
    } else {
        const int k = (blk - 6) * 256 + t;        // 0..511
        if (k < H2N) {
            float s = 0.f;
            #pragma unroll
            for (int j = 0; j < HOFD; j++) s += W3[k * HOFD + j] * Wc[j];
            g_w3c[k] = s;
        }
        if (blk == 6 && t == 0) {
            float s = 0.f;
            #pragma unroll
            for (int j = 0; j < HOFD; j++) s += b3[j] * Wc[j];
            g_w3c[H2N] = s + bc[0];
        }
    }
}

// ================= pair term + x->bf16 conversion (fused) =================
// one warp per batch row; lane owns columns (2*lane, 2*lane+1) of every feature
// pd[b] = sum_d x_d^T Wsym x_d;  also writes g_xh = bf16(x)
__global__ __launch_bounds__(256) void pairdot_conv(
    const float* __restrict__ x, float* __restrict__ pd,
    __nv_bfloat16* __restrict__ xh)
{
    __shared__ float Ws[NFEAT * NFEAT];   // 4KB
    for (int i = threadIdx.x; i < NFEAT * NFEAT; i += 256)
        Ws[i] = g_wsym[i];
    __syncthreads();

    const int warp = threadIdx.x >> 5, lane = threadIdx.x & 31;
    const int b = blockIdx.x * 8 + warp;
    const float2* xp = (const float2*)(x + (size_t)b * KIN) + lane;
    __nv_bfloat162* xo = (__nv_bfloat162*)(xh + (size_t)b * KIN) + lane;

    float xa[NFEAT], xb[NFEAT];
    #pragma unroll
    for (int n = 0; n < NFEAT; n++) {
        float2 v = xp[n * 32];             // coalesced 256B per feature
        xa[n] = v.x; xb[n] = v.y;
        __nv_bfloat162 h;
        h.x = __float2bfloat16(v.x);
        h.y = __float2bfloat16(v.y);
        xo[n * 32] = h;                    // coalesced 128B per feature
    }

    float acc = 0.f;
    #pragma unroll
    for (int n = 0; n < NFEAT; n++) {
        float ta = 0.f, tb = 0.f;
        const float4* wrow = (const float4*)&Ws[n * NFEAT];
        #pragma unroll
        for (int m4 = 0; m4 < NFEAT / 4; m4++) {
            float4 w = wrow[m4];
            const int m = m4 * 4;
            ta = fmaf(w.x, xa[m + 0], ta); tb = fmaf(w.x, xb[m + 0], tb);
            ta = fmaf(w.y, xa[m + 1], ta); tb = fmaf(w.y, xb[m + 1], tb);
            ta = fmaf(w.z, xa[m + 2], ta); tb = fmaf(w.z, xb[m + 2], tb);
            ta = fmaf(w.w, xa[m + 3], ta); tb = fmaf(w.w, xb[m + 3], tb);
        }
        acc = fmaf(xa[n], ta, acc);
        acc = fmaf(xb[n], tb, acc);
    }
    #pragma unroll
    for (int o = 16; o > 0; o >>= 1)
        acc += __shfl_down_sync(0xffffffffu, acc, o);
    if (lane == 0) pd[b] = acc;
}

// transpose W [K][N] -> oh [N][K] bf16; optional scale1[k] fold
template<int K, int N, bool SCALED>
__global__ __launch_bounds__(256) void conv_w(const float* __restrict__ W,
                                              __nv_bfloat16* __restrict__ oh) {
    __shared__ float t[32][33];
    const int lx = threadIdx.x & 31, ly = threadIdx.x >> 5;
    const int k0 = blockIdx.y * 32, n0 = blockIdx.x * 32;
    #pragma unroll
    for (int r = 0; r < 4; r++) {
        int k = k0 + ly + r * 8;
        float v = W[(size_t)k * N + n0 + lx];
        if (SCALED) v *= g_scale1[k];
        t[ly + r * 8][lx] = v;
    }
    __syncthreads();
    #pragma unroll
    for (int r = 0; r < 4; r++) {
        int n = n0 + ly + r * 8;
        oh[(size_t)n * K + k0 + lx] = __float2bfloat16(t[lx][ly + r * 8]);
    }
}

// bias2eff[n] += sum_k bias1v[k] * W2[k][n]
__global__ __launch_bounds__(512) void b2eff_acc(const float* __restrict__ W2) {
    const int n = threadIdx.x;
    const int k0 = blockIdx.x * 16;
    float a = 0.f;
    #pragma unroll
    for (int r = 0; r < 16; r++)
        a += g_bias1v[k0 + r] * W2[(size_t)(k0 + r) * H2N + n];
    atomicAdd(&g_b2eff[n], a);
}

// per-column sum/sumsq over bf16
__global__ void colreduce_bf16(const __nv_bfloat16* __restrict__ X,
                               int M, int N,
                               float* __restrict__ sum, float* __restrict__ sq) {
    const int lane = threadIdx.x & 31, ty = threadIdx.x >> 5;
    const int col = blockIdx.x * 32 + lane;
    const int rowsPer = M / gridDim.y;
    const int r0 = blockIdx.y * rowsPer;
    float s = 0.f, q = 0.f;
    for (int r = r0 + ty; r < r0 + rowsPer; r += 8) {
        float v = __bfloat162float(X[(size_t)r * N + col]);
        s += v; q += v * v;
    }
    __shared__ float ss[8][33], qs[8][33];
    ss[ty][lane] = s; qs[ty][lane] = q;
    __syncthreads();
    if (ty == 0) {
        #pragma unroll
        for (int t = 1; t < 8; t++) { s += ss[t][lane]; q += qs[t][lane]; }
        atomicAdd(&sum[col], s);
        atomicAdd(&sq[col], q);
    }
}

__global__ void colreduce(const float* __restrict__ X, int M, int N,
                          float* __restrict__ sum, float* __restrict__ sq) {
    const int lane = threadIdx.x & 31, ty = threadIdx.x >> 5;
    const int col = blockIdx.x * 32 + lane;
    const int rowsPer = M / gridDim.y;
    const int r0 = blockIdx.y * rowsPer;
    float s = 0.f, q = 0.f;
    for (int r = r0 + ty; r < r0 + rowsPer; r += 8) {
        float v = X[(size_t)r * N + col];
        s += v; q += v * v;
    }
    __shared__ float ss[8][33], qs[8][33];
    ss[ty][lane] = s; qs[ty][lane] = q;
    __syncthreads();
    if (ty == 0) {
        #pragma unroll
        for (int t = 1; t < 8; t++) { s += ss[t][lane]; q += qs[t][lane]; }
        atomicAdd(&sum[col], s);
        atomicAdd(&sq[col], q);
    }
}

__global__ void stats_kernel(const float* __restrict__ sum,
                             const float* __restrict__ sq,
                             const float* __restrict__ g,
                             const float* __restrict__ beta,
                             int N, float* __restrict__ scale,
                             float* __restrict__ bOut) {
    int j = blockIdx.x * blockDim.x + threadIdx.x;
    if (j >= N) return;
    const float invM = 1.f / (float)B_SZ;
    float m = sum[j] * invM;
    float v = sq[j] * invM - m * m;
    float sc = g[j] * rsqrtf(v + BN_EPS);
    scale[j] = sc;
    bOut[j] = beta[j] - m * sc;
}

// out[b] = (BN2(h2) . w3c) + c0 + pd[b]
__global__ void final_kernel(const float* __restrict__ h2, float* __restrict__ out) {
    const int gw = (blockIdx.x * blockDim.x + threadIdx.x) >> 5;
    const int lane = threadIdx.x & 31;
    if (gw >= B_SZ) return;
    const float* h = h2 + (size_t)gw * H2N;
    float acc = 0.f;
    #pragma unroll 4
    for (int k = lane; k < H2N; k += 32)
        acc += fmaf(h[k], g_scale2[k], g_bias2v[k]) * g_w3c[k];
    #pragma unroll
    for (int o = 16; o > 0; o >>= 1)
        acc += __shfl_down_sync(0xffffffffu, acc, o);
    if (lane == 0) out[gw] = acc + g_w3c[H2N] + g_pd[gw];
}

// ================= launch =================
extern "C" void kernel_launch(void* const* d_in, const int* in_sizes, int n_in,
                              void* d_out, int out_size) {
    const float* x     = (const float*)d_in[0];
    const float* W1    = (const float*)d_in[1];
    const float* b1    = (const float*)d_in[2];
    const float* g1    = (const float*)d_in[3];
    const float* beta1 = (const float*)d_in[4];
    const float* W2    = (const float*)d_in[5];
    const float* b2    = (const float*)d_in[6];
    const float* g2    = (const float*)d_in[7];
    const float* beta2 = (const float*)d_in[8];
    const float* W3    = (const float*)d_in[9];
    const float* b3    = (const float*)d_in[10];
    const float* Wc    = (const float*)d_in[11];
    const float* bc    = (const float*)d_in[12];
    float* out = (float*)d_out;

    __nv_bfloat16 *p_xh, *p_w1h, *p_a1h, *p_w2h;
    float *p_h2, *p_pd, *p_sum1, *p_sq1, *p_scale1, *p_bias1v;
    float *p_sum2, *p_sq2, *p_scale2, *p_bias2v, *p_b2eff;
    cudaGetSymbolAddress((void**)&p_xh, g_xh);
    cudaGetSymbolAddress((void**)&p_w1h, g_w1h);
    cudaGetSymbolAddress((void**)&p_a1h, g_a1h);
    cudaGetSymbolAddress((void**)&p_w2h, g_w2h);
    cudaGetSymbolAddress((void**)&p_h2, g_h2);
    cudaGetSymbolAddress((void**)&p_pd, g_pd);
    cudaGetSymbolAddress((void**)&p_sum1, g_sum1);
    cudaGetSymbolAddress((void**)&p_sq1, g_sq1);
    cudaGetSymbolAddress((void**)&p_scale1, g_scale1);
    cudaGetSymbolAddress((void**)&p_bias1v, g_bias1v);
    cudaGetSymbolAddress((void**)&p_sum2, g_sum2);
    cudaGetSymbolAddress((void**)&p_sq2, g_sq2);
    cudaGetSymbolAddress((void**)&p_scale2, g_scale2);
    cudaGetSymbolAddress((void**)&p_bias2v, g_bias2v);
    cudaGetSymbolAddress((void**)&p_b2eff, g_b2eff);

    const int GSM = 3 * 32768 + 1024;  // 3 stages of 32KB + alignment slack
    cudaFuncSetAttribute(gemm_mma<KIN, H1, 0>,
                         cudaFuncAttributeMaxDynamicSharedMemorySize, GSM);
    cudaFuncSetAttribute(gemm_mma<H1, H2N, 1>,
                         cudaFuncAttributeMaxDynamicSharedMemorySize, GSM);

    // launch order keeps gemm1 as 4th launch (ncu capture slot)
    prep_kernel<<<8, 256>>>(b2, Wc, W3, b3, bc);
    pairdot_conv<<<B_SZ / 8, 256>>>(x, p_pd, p_xh);
    conv_w<KIN, H1, false><<<dim3(H1 / 32, KIN / 32), 256>>>(W1, p_w1h);

    // layer 1: a1 = relu(x @ W1 + b1), bf16 out (pre-BN)   [4th launch: profiled]
    gemm_mma<KIN, H1, 0><<<dim3(H1 / 128, B_SZ / 128), 256, GSM>>>(
        p_xh, p_w1h, b1, p_a1h, nullptr);

    colreduce_bf16<<<dim3(H1 / 32, 64), 256>>>(p_a1h, B_SZ, H1, p_sum1, p_sq1);
    stats_kernel<<<4, 256>>>(p_sum1, p_sq1, g1, beta1, H1, p_scale1, p_bias1v);

    // fold BN1 into W2 (scale) and bias2eff (rank-1 bias term)
    conv_w<H1, H2N, true><<<dim3(H2N / 32, H1 / 32), 256>>>(W2, p_w2h);
    b2eff_acc<<<H1 / 16, 512>>>(W2);

    // layer 2: h2 = relu( a1 @ (scale1*W2) + b2eff ), fp32 out (pre-BN2)
    gemm_mma<H1, H2N, 1><<<dim3(H2N / 128, B_SZ / 128), 256, GSM>>>(
        p_a1h, p_w2h, p_b2eff, nullptr, p_h2);
    colreduce<<<dim3(H2N / 32, 64), 256>>>(p_h2, B_SZ, H2N, p_sum2, p_sq2);
    stats_kernel<<<2, 256>>>(p_sum2, p_sq2, g2, beta2, H2N, p_scale2, p_bias2v);

    // final: out = BN2(h2) @ (W3@Wc) + (b3@Wc + bc) + pairs@Wc_pairs
    final_kernel<<<(B_SZ * 32) / 256, 256>>>(p_h2, out);
}

// round 11
// speedup vs baseline: 9.2690x; 1.0076x over previous
#include <cuda_runtime.h>
#include <cuda_bf16.h>
#include <cstdint>

// ---------------- problem constants ----------------
#define B_SZ   16384
#define NFEAT  32
#define DDIM   64
#define KIN    2048     // NFEAT*DDIM
#define H1     1024
#define H2N    512
#define HOFD   64
#define NPAIRS 496
#define BN_EPS 1e-5f

// ---------------- scratch (device globals; no runtime alloc) ----------------
__device__ __nv_bfloat16 g_xh[(size_t)B_SZ * KIN];
__device__ __nv_bfloat16 g_w1h[(size_t)H1 * KIN];   // [N=H1][K=KIN] transposed
__device__ __nv_bfloat16 g_a1h[(size_t)B_SZ * H1];  // relu(x@W1+b1) bf16, pre-BN
__device__ __nv_bfloat16 g_w2h[(size_t)H2N * H1];   // [N=H2N][K=H1], scale1 folded
__device__ __nv_bfloat16 g_h2[(size_t)B_SZ * H2N];  // relu(.@W2'+b2eff) bf16, pre-BN2
__device__ float g_pd[B_SZ];
__device__ float g_wsym[NFEAT * NFEAT];             // symmetric half-weight matrix
__device__ float g_sum1[H1], g_sq1[H1], g_scale1[H1], g_bias1v[H1];
__device__ float g_sum2[H2N], g_sq2[H2N], g_scale2[H2N], g_bias2v[H2N];
__device__ float g_b2eff[H2N];
__device__ float g_w3c[H2N + 1];

// ================= PTX helpers (baseline ISA only) ========
__device__ __forceinline__ uint32_t smem_u32(const void* p) {
    uint32_t a;
    asm("{ .reg .u64 t; cvta.to.shared.u64 t, %1; cvt.u32.u64 %0, t; }"
        : "=r"(a) : "l"(p));
    return a;
}
__device__ __forceinline__ void cpa16(uint32_t s, const void* g) {
    asm volatile("cp.async.cg.shared.global [%0], [%1], 16;" :: "r"(s), "l"(g));
}
#define CP_COMMIT() asm volatile("cp.async.commit_group;" ::: "memory")
#define CP_WAIT1()  asm volatile("cp.async.wait_group 1;" ::: "memory")
#define SWZ(o)      ((o) ^ (((o) >> 3) & 0x70))

__device__ __forceinline__ void ldsm4(uint32_t& r0, uint32_t& r1,
                                      uint32_t& r2, uint32_t& r3, uint32_t a) {
    asm volatile("ldmatrix.sync.aligned.m8n8.x4.shared.b16 {%0,%1,%2,%3}, [%4];"
                 : "=r"(r0), "=r"(r1), "=r"(r2), "=r"(r3) : "r"(a));
}
__device__ __forceinline__ void mma16816(float* c,
                                         uint32_t a0, uint32_t a1, uint32_t a2, uint32_t a3,
                                         uint32_t b0, uint32_t b1) {
    asm volatile("mma.sync.aligned.m16n8k16.row.col.f32.bf16.bf16.f32 "
                 "{%0,%1,%2,%3}, {%4,%5,%6,%7}, {%8,%9}, {%0,%1,%2,%3};"
                 : "+f"(c[0]), "+f"(c[1]), "+f"(c[2]), "+f"(c[3])
                 : "r"(a0), "r"(a1), "r"(a2), "r"(a3), "r"(b0), "r"(b1));
}

// ================= single-pass bf16 HMMA GEMM + fused BN stats =============
// 128x128 tile, 8 warps (2x4, warp tile 64x32), 3-stage cp.async, 2 CTAs/SM.
// C = relu(A @ B^T + bias) written bf16; per-column sum/sum^2 atomically
// accumulated into sumP/sqP (for the following batchnorm stats pass).
template<int KDIM, int NTOT>
__global__ __launch_bounds__(256, 2) void gemm_mma(
    const __nv_bfloat16* __restrict__ A,
    const __nv_bfloat16* __restrict__ Bw,
    const float* __restrict__ bias,
    __nv_bfloat16* __restrict__ outH,
    float* __restrict__ sumP, float* __restrict__ sqP)
{
    constexpr int S = 3, BK = 64, BN = 128, BM = 128;
    constexpr int T = KDIM / BK;
    constexpr int STAGE_BYTES = (BM + BN) * 128;  // 32KB: A 16K + B 16K (128B rows)

    extern __shared__ char smraw[];
    const uint32_t sb = (smem_u32(smraw) + 1023) & ~1023u;
    const int tid = threadIdx.x;
    const int wid = tid >> 5, lane = tid & 31;
    const int wm0 = (wid >> 2) * 64;        // 2 warp rows  (m: 0 / 64)
    const int wn0 = (wid & 3) * 32;         // 4 warp cols  (n: 0..96)
    const int m0 = blockIdx.y * BM, n0 = blockIdx.x * BN;

    auto load_stage = [&](int gs) {
        const uint32_t sA = sb + (gs % S) * STAGE_BYTES;
        const uint32_t sB = sA + BM * 128;
        const int kk = gs * BK;
        const __nv_bfloat16* Ab = A + (size_t)m0 * KDIM + kk;
        const __nv_bfloat16* Bb = Bw + (size_t)n0 * KDIM + kk;
        #pragma unroll
        for (int t = 0; t < BM * 8 / 256; t++) {          // 4 iters
            int c = tid + t * 256;
            int r = c >> 3, ch = c & 7;
            cpa16(sA + SWZ(r * 128 + ch * 16), Ab + (size_t)r * KDIM + ch * 8);
        }
        #pragma unroll
        for (int t = 0; t < BN * 8 / 256; t++) {          // 4 iters
            int c = tid + t * 256;
            int r = c >> 3, ch = c & 7;
            cpa16(sB + SWZ(r * 128 + ch * 16), Bb + (size_t)r * KDIM + ch * 8);
        }
    };

    // prologue: stages 0,1 in flight (prefetch distance 2)
    load_stage(0); CP_COMMIT();
    load_stage(1); CP_COMMIT();

    float acc[4][4][4];
    #pragma unroll
    for (int i = 0; i < 4; i++)
        #pragma unroll
        for (int j = 0; j < 4; j++)
            #pragma unroll
            for (int r = 0; r < 4; r++) acc[i][j][r] = 0.f;

    // per-lane ldmatrix row components (byte offsets within tile, pre-swizzle)
    const int aRowOff = (wm0 + (lane & 15)) * 128 + (lane >> 4) * 16;
    const int bRowBase = (wn0 + (lane & 7) + ((lane >> 4) << 3)) * 128 +
                         (((lane >> 3) & 1) << 4);

    for (int i = 0; i < T; ++i) {
        CP_WAIT1();
        __syncthreads();   // all warps done reading buffer (i-1) before refill
        // issue next stage's loads FIRST so DMA overlaps the whole MMA body
        const int ns = i + 2;
        if (ns < T) load_stage(ns);
        CP_COMMIT();
        const uint32_t sA = sb + (i % S) * STAGE_BYTES;
        const uint32_t sB = sA + BM * 128;
        #pragma unroll
        for (int ks = 0; ks < 4; ks++) {
            const int kb = ks * 32;   // 16 elems * 2B per k-step
            uint32_t a[4][4];
            #pragma unroll
            for (int mi = 0; mi < 4; mi++)
                ldsm4(a[mi][0], a[mi][1], a[mi][2], a[mi][3],
                      sA + SWZ(aRowOff + mi * 16 * 128 + kb));
            uint32_t bf[2][4];
            #pragma unroll
            for (int gg = 0; gg < 2; gg++)
                ldsm4(bf[gg][0], bf[gg][1], bf[gg][2], bf[gg][3],
                      sB + SWZ(bRowBase + gg * 16 * 128 + kb));
            #pragma unroll
            for (int mi = 0; mi < 4; mi++)
                #pragma unroll
                for (int j = 0; j < 4; j++)
                    mma16816(acc[mi][j], a[mi][0], a[mi][1], a[mi][2], a[mi][3],
                             bf[j >> 1][(j & 1) * 2], bf[j >> 1][(j & 1) * 2 + 1]);
        }
    }

    // ---------------- epilogue: relu+bias, bf16 store, fused col stats -----
    float csum[4][2], csq[4][2];
    #pragma unroll
    for (int j = 0; j < 4; j++) { csum[j][0] = csum[j][1] = csq[j][0] = csq[j][1] = 0.f; }

    #pragma unroll
    for (int j = 0; j < 4; j++) {
        const int col = n0 + wn0 + j * 8 + (lane & 3) * 2;
        const float bi0 = bias[col], bi1 = bias[col + 1];
        #pragma unroll
        for (int mi = 0; mi < 4; mi++) {
            const int row = m0 + wm0 + mi * 16 + (lane >> 2);
            #pragma unroll
            for (int h = 0; h < 2; h++) {   // h=0: row, h=1: row+8
                const int rr = row + h * 8;
                const float v0 = fmaxf(acc[mi][j][2 * h + 0] + bi0, 0.f);
                const float v1 = fmaxf(acc[mi][j][2 * h + 1] + bi1, 0.f);
                __nv_bfloat162 ph;
                ph.x = __float2bfloat16(v0);
                ph.y = __float2bfloat16(v1);
                *(__nv_bfloat162*)(outH + (size_t)rr * NTOT + col) = ph;
                csum[j][0] += v0; csq[j][0] = fmaf(v0, v0, csq[j][0]);
                csum[j][1] += v1; csq[j][1] = fmaf(v1, v1, csq[j][1]);
            }
        }
    }
    // reduce across the 8 lanes sharing each column (stride-4 lane groups)
    #pragma unroll
    for (int j = 0; j < 4; j++)
        #pragma unroll
        for (int c = 0; c < 2; c++) {
            #pragma unroll
            for (int o = 16; o >= 4; o >>= 1) {
                csum[j][c] += __shfl_down_sync(0xffffffffu, csum[j][c], o);
                csq[j][c]  += __shfl_down_sync(0xffffffffu, csq[j][c],  o);
            }
        }
    if (lane < 4) {
        #pragma unroll
        for (int j = 0; j < 4; j++)
            #pragma unroll
            for (int c = 0; c < 2; c++) {
                const int col = n0 + wn0 + j * 8 + lane * 2 + c;
                atomicAdd(&sumP[col], csum[j][c]);
                atomicAdd(&sqP[col],  csq[j][c]);
            }
    }
}

// ================= merged prep kernel =================
// blk 0-3: zero stats + b2eff init; blk 4-5: wsym; blk 6-7: w3c
__global__ __launch_bounds__(256) void prep_kernel(
    const float* __restrict__ b2, const float* __restrict__ Wc,
    const float* __restrict__ W3, const float* __restrict__ b3,
    const float* __restrict__ bc)
{
    const int t = threadIdx.x, blk = blockIdx.x;
    if (blk < 4) {
        const int i = blk * 256 + t;
        if (i < H1)  { g_sum1[i] = 0.f; g_sq1[i] = 0.f; }
        if (i < H2N) { g_sum2[i] = 0.f; g_sq2[i] = 0.f; g_b2eff[i] = b2[i]; }
    } else if (blk < 6) {
        const int p = (blk - 4) * 256 + t;        // 0..511
        const int d1 = p, d2 = p + 512;           // zero diagonal entries
        if ((d1 >> 5) == (d1 & 31)) g_wsym[d1] = 0.f;
        if ((d2 >> 5) == (d2 & 31)) g_wsym[d2] = 0.f;
        if (p < NPAIRS) {
            int i = 0, rem = p;
            while (rem >= NFEAT - 1 - i) { rem -= NFEAT - 1 - i; i++; }
            const int j = i + 1 + rem;
            const float hw = 0.5f * Wc[HOFD + p];
            g_wsym[i * NFEAT + j] = hw;
            g_wsym[j * NFEAT + i] = hw;
        }
    } else {
        const int k = (blk - 6) * 256 + t;        // 0..511
        if (k < H2N) {
            float s = 0.f;
            #pragma unroll
            for (int j = 0; j < HOFD; j++) s += W3[k * HOFD + j] * Wc[j];
            g_w3c[k] = s;
        }
        if (blk == 6 && t == 0) {
            float s = 0.f;
            #pragma unroll
            for (int j = 0; j < HOFD; j++) s += b3[j] * Wc[j];
            g_w3c[H2N] = s + bc[0];
        }
    }
}

// ================= pair term + x->bf16 conversion (fused) =================
__global__ __launch_bounds__(256) void pairdot_conv(
    const float* __restrict__ x, float* __restrict__ pd,
    __nv_bfloat16* __restrict__ xh)
{
    __shared__ float Ws[NFEAT * NFEAT];   // 4KB
    for (int i = threadIdx.x; i < NFEAT * NFEAT; i += 256)
        Ws[i] = g_wsym[i];
    __syncthreads();

    const int warp = threadIdx.x >> 5, lane = threadIdx.x & 31;
    const int b = blockIdx.x * 8 + warp;
    const float2* xp = (const float2*)(x + (size_t)b * KIN) + lane;
    __nv_bfloat162* xo = (__nv_bfloat162*)(xh + (size_t)b * KIN) + lane;

    float xa[NFEAT], xb[NFEAT];
    #pragma unroll
    for (int n = 0; n < NFEAT; n++) {
        float2 v = xp[n * 32];             // coalesced 256B per feature
        xa[n] = v.x; xb[n] = v.y;
        __nv_bfloat162 h;
        h.x = __float2bfloat16(v.x);
        h.y = __float2bfloat16(v.y);
        xo[n * 32] = h;                    // coalesced 128B per feature
    }

    float acc = 0.f;
    #pragma unroll
    for (int n = 0; n < NFEAT; n++) {
        float ta = 0.f, tb = 0.f;
        const float4* wrow = (const float4*)&Ws[n * NFEAT];
        #pragma unroll
        for (int m4 = 0; m4 < NFEAT / 4; m4++) {
            float4 w = wrow[m4];
            const int m = m4 * 4;
            ta = fmaf(w.x, xa[m + 0], ta); tb = fmaf(w.x, xb[m + 0], tb);
            ta = fmaf(w.y, xa[m + 1], ta); tb = fmaf(w.y, xb[m + 1], tb);
            ta = fmaf(w.z, xa[m + 2], ta); tb = fmaf(w.z, xb[m + 2], tb);
            ta = fmaf(w.w, xa[m + 3], ta); tb = fmaf(w.w, xb[m + 3], tb);
        }
        acc = fmaf(xa[n], ta, acc);
        acc = fmaf(xb[n], tb, acc);
    }
    #pragma unroll
    for (int o = 16; o > 0; o >>= 1)
        acc += __shfl_down_sync(0xffffffffu, acc, o);
    if (lane == 0) pd[b] = acc;
}

// transpose W [K][N] -> oh [N][K] bf16; optional scale1[k] fold
template<int K, int N, bool SCALED>
__global__ __launch_bounds__(256) void conv_w(const float* __restrict__ W,
                                              __nv_bfloat16* __restrict__ oh) {
    __shared__ float t[32][33];
    const int lx = threadIdx.x & 31, ly = threadIdx.x >> 5;
    const int k0 = blockIdx.y * 32, n0 = blockIdx.x * 32;
    #pragma unroll
    for (int r = 0; r < 4; r++) {
        int k = k0 + ly + r * 8;
        float v = W[(size_t)k * N + n0 + lx];
        if (SCALED) v *= g_scale1[k];
        t[ly + r * 8][lx] = v;
    }
    __syncthreads();
    #pragma unroll
    for (int r = 0; r < 4; r++) {
        int n = n0 + ly + r * 8;
        oh[(size_t)n * K + k0 + lx] = __float2bfloat16(t[lx][ly + r * 8]);
    }
}

// bias2eff[n] += sum_k bias1v[k] * W2[k][n]
__global__ __launch_bounds__(512) void b2eff_acc(const float* __restrict__ W2) {
    const int n = threadIdx.x;
    const int k0 = blockIdx.x * 16;
    float a = 0.f;
    #pragma unroll
    for (int r = 0; r < 16; r++)
        a += g_bias1v[k0 + r] * W2[(size_t)(k0 + r) * H2N + n];
    atomicAdd(&g_b2eff[n], a);
}

__global__ void stats_kernel(const float* __restrict__ sum,
                             const float* __restrict__ sq,
                             const float* __restrict__ g,
                             const float* __restrict__ beta,
                             int N, float* __restrict__ scale,
                             float* __restrict__ bOut) {
    int j = blockIdx.x * blockDim.x + threadIdx.x;
    if (j >= N) return;
    const float invM = 1.f / (float)B_SZ;
    float m = sum[j] * invM;
    float v = sq[j] * invM - m * m;
    float sc = g[j] * rsqrtf(v + BN_EPS);
    scale[j] = sc;
    bOut[j] = beta[j] - m * sc;
}

// out[b] = (BN2(h2) . w3c) + c0 + pd[b]   (h2 stored bf16)
__global__ void final_kernel(const __nv_bfloat16* __restrict__ h2,
                             float* __restrict__ out) {
    const int gw = (blockIdx.x * blockDim.x + threadIdx.x) >> 5;
    const int lane = threadIdx.x & 31;
    if (gw >= B_SZ) return;
    const __nv_bfloat162* h = (const __nv_bfloat162*)(h2 + (size_t)gw * H2N) + lane;
    float acc = 0.f;
    #pragma unroll
    for (int it = 0; it < H2N / 64; it++) {
        const int k = it * 64 + lane * 2;
        __nv_bfloat162 hv = h[it * 32];
        float v0 = __bfloat162float(hv.x), v1 = __bfloat162float(hv.y);
        acc += fmaf(v0, g_scale2[k],     g_bias2v[k])     * g_w3c[k];
        acc += fmaf(v1, g_scale2[k + 1], g_bias2v[k + 1]) * g_w3c[k + 1];
    }
    #pragma unroll
    for (int o = 16; o > 0; o >>= 1)
        acc += __shfl_down_sync(0xffffffffu, acc, o);
    if (lane == 0) out[gw] = acc + g_w3c[H2N] + g_pd[gw];
}

// ================= launch =================
extern "C" void kernel_launch(void* const* d_in, const int* in_sizes, int n_in,
                              void* d_out, int out_size) {
    const float* x     = (const float*)d_in[0];
    const float* W1    = (const float*)d_in[1];
    const float* b1    = (const float*)d_in[2];
    const float* g1    = (const float*)d_in[3];
    const float* beta1 = (const float*)d_in[4];
    const float* W2    = (const float*)d_in[5];
    const float* b2    = (const float*)d_in[6];
    const float* g2    = (const float*)d_in[7];
    const float* beta2 = (const float*)d_in[8];
    const float* W3    = (const float*)d_in[9];
    const float* b3    = (const float*)d_in[10];
    const float* Wc    = (const float*)d_in[11];
    const float* bc    = (const float*)d_in[12];
    float* out = (float*)d_out;

    __nv_bfloat16 *p_xh, *p_w1h, *p_a1h, *p_w2h, *p_h2;
    float *p_pd, *p_sum1, *p_sq1, *p_scale1, *p_bias1v;
    float *p_sum2, *p_sq2, *p_scale2, *p_bias2v, *p_b2eff;
    cudaGetSymbolAddress((void**)&p_xh, g_xh);
    cudaGetSymbolAddress((void**)&p_w1h, g_w1h);
    cudaGetSymbolAddress((void**)&p_a1h, g_a1h);
    cudaGetSymbolAddress((void**)&p_w2h, g_w2h);
    cudaGetSymbolAddress((void**)&p_h2, g_h2);
    cudaGetSymbolAddress((void**)&p_pd, g_pd);
    cudaGetSymbolAddress((void**)&p_sum1, g_sum1);
    cudaGetSymbolAddress((void**)&p_sq1, g_sq1);
    cudaGetSymbolAddress((void**)&p_scale1, g_scale1);
    cudaGetSymbolAddress((void**)&p_bias1v, g_bias1v);
    cudaGetSymbolAddress((void**)&p_sum2, g_sum2);
    cudaGetSymbolAddress((void**)&p_sq2, g_sq2);
    cudaGetSymbolAddress((void**)&p_scale2, g_scale2);
    cudaGetSymbolAddress((void**)&p_bias2v, g_bias2v);
    cudaGetSymbolAddress((void**)&p_b2eff, g_b2eff);

    const int GSM = 3 * 32768 + 1024;  // 3 stages of 32KB + alignment slack
    cudaFuncSetAttribute(gemm_mma<KIN, H1>,
                         cudaFuncAttributeMaxDynamicSharedMemorySize, GSM);
    cudaFuncSetAttribute(gemm_mma<H1, H2N>,
                         cudaFuncAttributeMaxDynamicSharedMemorySize, GSM);

    // launch order keeps gemm1 as 4th launch (ncu capture slot)
    prep_kernel<<<8, 256>>>(b2, Wc, W3, b3, bc);
    pairdot_conv<<<B_SZ / 8, 256>>>(x, p_pd, p_xh);
    conv_w<KIN, H1, false><<<dim3(H1 / 32, KIN / 32), 256>>>(W1, p_w1h);

    // layer 1: a1 = relu(x @ W1 + b1), bf16 out + fused BN1 stats  [profiled]
    gemm_mma<KIN, H1><<<dim3(H1 / 128, B_SZ / 128), 256, GSM>>>(
        p_xh, p_w1h, b1, p_a1h, p_sum1, p_sq1);

    stats_kernel<<<4, 256>>>(p_sum1, p_sq1, g1, beta1, H1, p_scale1, p_bias1v);

    // fold BN1 into W2 (scale) and bias2eff (rank-1 bias term)
    conv_w<H1, H2N, true><<<dim3(H2N / 32, H1 / 32), 256>>>(W2, p_w2h);
    b2eff_acc<<<H1 / 16, 512>>>(W2);

    // layer 2: h2 = relu( a1 @ (scale1*W2) + b2eff ), bf16 out + fused BN2 stats
    gemm_mma<H1, H2N><<<dim3(H2N / 128, B_SZ / 128), 256, GSM>>>(
        p_a1h, p_w2h, p_b2eff, p_h2, p_sum2, p_sq2);
    stats_kernel<<<2, 256>>>(p_sum2, p_sq2, g2, beta2, H2N, p_scale2, p_bias2v);

    // final: out = BN2(h2) @ (W3@Wc) + (b3@Wc + bc) + pairs@Wc_pairs
    final_kernel<<<(B_SZ * 32) / 256, 256>>>(p_h2, out);
}